// round 1
// baseline (speedup 1.0000x reference)
#include <cuda_runtime.h>
#include <cstdint>

#define D_DIM 512
#define K_DIM 32
#define P_DIM 528            // K*(K+1)/2
#define MAXN  100352         // multiple of 128, >= 100000
#define GAMMA 0.01f
#define TOLF  1e-6f
#define GUESS_RATIO (1.0f - 0.001f)

// ---------------- device scratch (no allocs allowed) ----------------
__device__ float g_coord[(size_t)MAXN * K_DIM];   // 12.8 MB
__device__ float g_kv[MAXN];
__device__ float g_Vt[P_DIM * D_DIM];             // 1.08 MB, Vt[p][d] = V[d][p]
__device__ float g_xmuU[K_DIM];
__device__ float g_xcU[K_DIM];
__device__ float g_change[D_DIM];

// ---------------- kernel A: small vectors ----------------
__global__ void k_init(const float* __restrict__ U,
                       const float* __restrict__ zmu,
                       const float* __restrict__ xc) {
    __shared__ float s_xmuU[K_DIM], s_xcU[K_DIM];
    int t = threadIdx.x;
    if (t < 64) {
        int j = t & 31;
        bool is_mu = t < 32;
        const float* v = is_mu ? zmu : xc;
        float s = 0.f;
        for (int d = 0; d < D_DIM; ++d) s = fmaf(v[d], U[d * K_DIM + j], s);
        if (is_mu) { s_xmuU[j] = s; g_xmuU[j] = s; }
        else       { s_xcU[j]  = s; g_xcU[j]  = s; }
    }
    __syncthreads();
    for (int d = t; d < D_DIM; d += blockDim.x) {
        float s = 0.f;
        #pragma unroll
        for (int j = 0; j < K_DIM; ++j)
            s = fmaf(s_xcU[j] - s_xmuU[j], U[d * K_DIM + j], s);
        g_change[d] = xc[d] - zmu[d] - s;
    }
}

// ---------------- kernel T: transpose V (D x P) -> Vt (P x D) ----------------
__global__ void k_transpose(const float* __restrict__ V) {
    int p = blockIdx.x;
    for (int d = threadIdx.x; d < D_DIM; d += blockDim.x)
        g_Vt[p * D_DIM + d] = V[d * P_DIM + p];
}

// ---------------- secant f ----------------
__device__ __forceinline__ float secf(float x, float egz, float zp) {
    float t = 1.f - egz * expf(-GAMMA * x);
    return t * t * x - zp;
}

// ---------------- kernel B: per-row stats (1 warp / row) ----------------
__global__ __launch_bounds__(256) void k_rowstats(
    const float* __restrict__ Z_all, const float* __restrict__ U,
    const float* __restrict__ zmu, const int* __restrict__ choice, int N) {

    __shared__ float Zs[8][D_DIM];
    __shared__ float zmuS[D_DIM];
    __shared__ float xmuUS[K_DIM], xcUS[K_DIM];

    int tid = threadIdx.x;
    for (int d = tid; d < D_DIM; d += 256) zmuS[d] = zmu[d];
    if (tid < K_DIM) { xmuUS[tid] = g_xmuU[tid]; xcUS[tid] = g_xcU[tid]; }
    __syncthreads();

    int w = tid >> 5, lane = tid & 31;
    int n = blockIdx.x * 8 + w;
    if (n >= N) return;
    size_t row = (size_t)choice[n];

    const float4* Zrow = (const float4*)(Z_all + row * D_DIM);
    float4* Zs4 = (float4*)Zs[w];
    const float4* zmu4 = (const float4*)zmuS;

    float zn = 0.f;
    #pragma unroll
    for (int i = 0; i < 4; ++i) {
        int c4 = lane + 32 * i;
        float4 z = Zrow[c4];
        Zs4[c4] = z;
        float4 m = zmu4[c4];
        float dx = z.x - m.x, dy = z.y - m.y, dz = z.z - m.z, dw = z.w - m.w;
        zn += dx * dx + dy * dy + dz * dz + dw * dw;
    }
    __syncwarp();
    #pragma unroll
    for (int o = 16; o; o >>= 1) zn += __shfl_xor_sync(~0u, zn, o);

    // ZU: lane owns j-quad jq (4 cols), partial over d stride 4 (dg)
    int jq = lane & 7, dg = lane >> 3;
    const float4* U4 = (const float4*)U;   // [D][8] float4
    float4 acc = make_float4(0.f, 0.f, 0.f, 0.f);
    #pragma unroll 4
    for (int d = dg; d < D_DIM; d += 4) {
        float4 u = U4[d * 8 + jq];
        float z = Zs[w][d];
        acc.x = fmaf(z, u.x, acc.x);
        acc.y = fmaf(z, u.y, acc.y);
        acc.z = fmaf(z, u.z, acc.z);
        acc.w = fmaf(z, u.w, acc.w);
    }
    #pragma unroll
    for (int o = 8; o <= 16; o <<= 1) {
        acc.x += __shfl_xor_sync(~0u, acc.x, o);
        acc.y += __shfl_xor_sync(~0u, acc.y, o);
        acc.z += __shfl_xor_sync(~0u, acc.z, o);
        acc.w += __shfl_xor_sync(~0u, acc.w, o);
    }

    float4 xm = ((const float4*)xmuUS)[jq];
    float dx = acc.x - xm.x, dy = acc.y - xm.y, dz = acc.z - xm.z, dw = acc.w - xm.w;
    float s = dx * dx + dy * dy + dz * dz + dw * dw;
    float zun = (dg == 0) ? s : 0.f;
    #pragma unroll
    for (int o = 16; o; o >>= 1) zun += __shfl_xor_sync(~0u, zun, o);

    if (dg == 0) {
        float4 xcv = ((const float4*)xcUS)[jq];
        float4 cd = make_float4(acc.x - xcv.x, acc.y - xcv.y,
                                acc.z - xcv.z, acc.w - xcv.w);
        ((float4*)(g_coord + (size_t)n * K_DIM))[jq] = cd;
    }

    if (lane == 0) {
        float zp = zn - zun;                 // ZUperp_norm2
        float egz = expf(-GAMMA * zun);
        float x_m2 = zp * GUESS_RATIO, x_m1 = zp;
        float f_m2 = secf(x_m2, egz, zp);
        for (int it = 0; it < 100; ++it) {
            float f_m1 = secf(x_m1, egz, zp);
            float fd = f_m1 - f_m2;
            if (fabsf(fd) < TOLF) fd = (fd >= 0.f) ? TOLF : -TOLF;
            float x = x_m1 - f_m1 * (x_m1 - x_m2) / fd;
            float st = fabsf(x - x_m1);
            x_m2 = x_m1; f_m2 = f_m1; x_m1 = x;
            if (st < TOLF) break;
        }
        g_kv[n] = expf(-GAMMA * (zun + x_m1));
    }
}

// ---------------- kernel C: GEMM C = H @ Vt + fused epilogue ----------------
// Tile: 128 rows x 128 cols, K-chunk 8; 256 threads, 8x8 microtile each.
#define MT 128
#define NT 128
#define PT 8
__global__ __launch_bounds__(256) void k_gemm(
    const float* __restrict__ Z_all, const int* __restrict__ choice,
    float* __restrict__ out, int N) {

    __shared__ float coordT[K_DIM][133];   // transposed, padded
    __shared__ float VtS[PT][NT];
    __shared__ float HS[PT][MT];
    __shared__ float changeS[NT];
    __shared__ float kvS[MT];
    __shared__ unsigned char iuI[P_DIM], iuJ[P_DIM];

    int tid = threadIdx.x;
    int m0 = blockIdx.x * MT;
    int d0 = blockIdx.y * NT;

    if (tid < K_DIM) {
        int i = tid;
        int off = i * K_DIM - (i * (i - 1)) / 2;
        for (int j = i; j < K_DIM; ++j) {
            iuI[off + j - i] = (unsigned char)i;
            iuJ[off + j - i] = (unsigned char)j;
        }
    }
    if (tid < NT) changeS[tid] = g_change[d0 + tid];
    if (tid >= 128 && tid < 256) {
        int m = tid - 128;
        kvS[m] = (m0 + m < N) ? g_kv[m0 + m] : 0.f;
    }
    for (int e = tid; e < MT * K_DIM; e += 256) {
        int m = e >> 5, c = e & 31;
        coordT[c][m] = (m0 + m < N) ? g_coord[(size_t)(m0 + m) * K_DIM + c] : 0.f;
    }
    __syncthreads();

    int tx = tid & 15, ty = tid >> 4;
    int mx = ty * 8, nx = tx * 8;
    float acc[8][8] = {};

    for (int pc = 0; pc < P_DIM / PT; ++pc) {
        { // load Vt chunk (coalesced float4)
            int e = tid * 4;
            int p = e >> 7, dd = e & 127;
            *(float4*)&VtS[p][dd] =
                *(const float4*)&g_Vt[(pc * PT + p) * D_DIM + d0 + dd];
        }
        #pragma unroll
        for (int q = 0; q < 4; ++q) { // H on the fly from coord tile
            int e = tid + 256 * q;
            int p = e >> 7, m = e & 127;
            int pg = pc * PT + p;
            HS[p][m] = coordT[iuI[pg]][m] * coordT[iuJ[pg]][m];
        }
        __syncthreads();
        #pragma unroll
        for (int pp = 0; pp < PT; ++pp) {
            float4 a0 = *(float4*)&HS[pp][mx];
            float4 a1 = *(float4*)&HS[pp][mx + 4];
            float4 b0 = *(float4*)&VtS[pp][nx];
            float4 b1 = *(float4*)&VtS[pp][nx + 4];
            float a[8] = {a0.x, a0.y, a0.z, a0.w, a1.x, a1.y, a1.z, a1.w};
            float b[8] = {b0.x, b0.y, b0.z, b0.w, b1.x, b1.y, b1.z, b1.w};
            #pragma unroll
            for (int mi = 0; mi < 8; ++mi)
                #pragma unroll
                for (int ni = 0; ni < 8; ++ni)
                    acc[mi][ni] = fmaf(a[mi], b[ni], acc[mi][ni]);
        }
        __syncthreads();
    }

    // epilogue: out[row] = Z[row] + kv * (change + acc)
    #pragma unroll
    for (int mi = 0; mi < 8; ++mi) {
        int nrow = m0 + mx + mi;
        if (nrow >= N) continue;
        size_t row = (size_t)choice[nrow];
        float kv = kvS[mx + mi];
        size_t base = row * D_DIM + d0 + nx;
        float4 z0 = *(const float4*)&Z_all[base];
        float4 z1 = *(const float4*)&Z_all[base + 4];
        float4 o0, o1;
        o0.x = z0.x + kv * (changeS[nx + 0] + acc[mi][0]);
        o0.y = z0.y + kv * (changeS[nx + 1] + acc[mi][1]);
        o0.z = z0.z + kv * (changeS[nx + 2] + acc[mi][2]);
        o0.w = z0.w + kv * (changeS[nx + 3] + acc[mi][3]);
        o1.x = z1.x + kv * (changeS[nx + 4] + acc[mi][4]);
        o1.y = z1.y + kv * (changeS[nx + 5] + acc[mi][5]);
        o1.z = z1.z + kv * (changeS[nx + 6] + acc[mi][6]);
        o1.w = z1.w + kv * (changeS[nx + 7] + acc[mi][7]);
        *(float4*)&out[base] = o0;
        *(float4*)&out[base + 4] = o1;
    }
}

// ---------------- launch ----------------
extern "C" void kernel_launch(void* const* d_in, const int* in_sizes, int n_in,
                              void* d_out, int out_size) {
    const float* Z_all = (const float*)d_in[0];
    const float* U     = (const float*)d_in[1];
    const float* V     = (const float*)d_in[2];
    const float* zmu   = (const float*)d_in[3];
    const float* xc    = (const float*)d_in[4];
    const int*   choice= (const int*)d_in[5];
    int N = in_sizes[5];
    float* out = (float*)d_out;

    k_init<<<1, 512>>>(U, zmu, xc);
    k_transpose<<<P_DIM, 256>>>(V);
    k_rowstats<<<(N + 7) / 8, 256>>>(Z_all, U, zmu, choice, N);
    // base: output rows not in choice_index must equal Z_all
    cudaMemcpyAsync(d_out, d_in[0], (size_t)out_size * sizeof(float),
                    cudaMemcpyDeviceToDevice);
    dim3 grid((N + MT - 1) / MT, D_DIM / NT);
    k_gemm<<<grid, 256>>>(Z_all, choice, out, N);
}

// round 6
// speedup vs baseline: 2.1869x; 2.1869x over previous
#include <cuda_runtime.h>
#include <cuda_bf16.h>
#include <cstdint>

#define D_DIM 512
#define K_DIM 32
#define P_DIM 528            // K*(K+1)/2 = 33*16 exactly
#define MAXN  100352
#define GAMMA 0.01f
#define TOLF  1e-6f
#define GUESS_RATIO (1.0f - 0.001f)

#define NKS   33             // k-steps of 16
#define KSPC  11             // k-steps per bulk chunk
#define CHB   45056          // bytes per B chunk: 128 n * 11*16 k * 2B
#define MT    128

// ---------------- device scratch ----------------
__device__ float g_coord[(size_t)MAXN * K_DIM];
__device__ float g_kv[MAXN];
// B image: [4 nblk][3 kchunk][128 n][88 u32]  (k-pairs permuted within each 16)
__device__ __align__(16) uint32_t g_Vb[4 * 3 * 128 * 88];
__device__ float g_xmuU[K_DIM];
__device__ float g_xcU[K_DIM];
__device__ float g_change[D_DIM];

// ---------------- PTX helpers ----------------
__device__ __forceinline__ uint32_t smem_u32(const void* p) {
    uint32_t a;
    asm("{ .reg .u64 t; cvta.to.shared.u64 t, %1; cvt.u32.u64 %0, t; }" : "=r"(a) : "l"(p));
    return a;
}
#define MBAR_INIT(a, c) asm volatile("mbarrier.init.shared.b64 [%0], %1;" :: "r"(a), "r"(c) : "memory")
#define MBAR_EXPECT_TX(a, b) asm volatile("mbarrier.arrive.expect_tx.shared.b64 _, [%0], %1;" :: "r"(a), "r"(b) : "memory")
#define MBAR_WAIT(a, p) do { \
    uint32_t _m = (a), _p = (p), _d; \
    asm volatile("{ .reg .pred q; mbarrier.try_wait.parity.acquire.cta.shared::cta.b64 q, [%1], %2; selp.b32 %0,1,0,q; }" \
        : "=r"(_d) : "r"(_m), "r"(_p) : "memory"); \
    if (!_d) asm volatile("{ .reg .pred Q; WL%=: mbarrier.try_wait.parity.acquire.cta.shared::cta.b64 Q, [%0], %1, 0x989680; @Q bra.uni WD%=; bra.uni WL%=; WD%=: }" \
        :: "r"(_m), "r"(_p) : "memory"); \
} while (0)
#define FENCE_ASYNC() asm volatile("fence.proxy.async.shared::cta;" ::: "memory")

__device__ __forceinline__ void bulk_g2s(uint32_t dst, const void* src, uint32_t bytes, uint32_t mbar) {
    asm volatile("cp.async.bulk.shared::cta.global.mbarrier::complete_tx::bytes [%0], [%1], %2, [%3];"
        :: "r"(dst), "l"(src), "r"(bytes), "r"(mbar) : "memory");
}
__device__ __forceinline__ void mma16816(float* c, const uint32_t* a, const uint32_t* b) {
    asm volatile("mma.sync.aligned.m16n8k16.row.col.f32.bf16.bf16.f32 "
        "{%0,%1,%2,%3}, {%4,%5,%6,%7}, {%8,%9}, {%0,%1,%2,%3};"
        : "+f"(c[0]), "+f"(c[1]), "+f"(c[2]), "+f"(c[3])
        : "r"(a[0]), "r"(a[1]), "r"(a[2]), "r"(a[3]), "r"(b[0]), "r"(b[1]));
}
__device__ __forceinline__ uint32_t packbf(float a, float b) {
    __nv_bfloat162 r = __float22bfloat162_rn(make_float2(a, b));
    return *(uint32_t*)&r;
}

// ---------------- kernel A: small vectors ----------------
__global__ void k_init(const float* __restrict__ U,
                       const float* __restrict__ zmu,
                       const float* __restrict__ xc) {
    __shared__ float s_xmuU[K_DIM], s_xcU[K_DIM];
    int t = threadIdx.x;
    if (t < 64) {
        int j = t & 31;
        bool is_mu = t < 32;
        const float* v = is_mu ? zmu : xc;
        float s = 0.f;
        for (int d = 0; d < D_DIM; ++d) s = fmaf(v[d], U[d * K_DIM + j], s);
        if (is_mu) { s_xmuU[j] = s; g_xmuU[j] = s; }
        else       { s_xcU[j]  = s; g_xcU[j]  = s; }
    }
    __syncthreads();
    for (int d = t; d < D_DIM; d += blockDim.x) {
        float s = 0.f;
        #pragma unroll
        for (int j = 0; j < K_DIM; ++j)
            s = fmaf(s_xcU[j] - s_xmuU[j], U[d * K_DIM + j], s);
        g_change[d] = xc[d] - zmu[d] - s;
    }
}

// ---------------- kernel P: build permuted bf16 B image ----------------
// position q in 0..7 within a 16-k step maps to original k = 2*(q>>1) + 8*(q&1)
__global__ void k_prepV(const float* __restrict__ V) {
    int pos = blockIdx.x * 132 + threadIdx.x;     // 0..263 (u32 within d-row)
    if (threadIdx.x >= 132) return;
    int d = blockIdx.y;
    int ks = pos >> 3, q = pos & 7;
    int k = ks * 16 + 2 * (q >> 1) + 8 * (q & 1);
    float2 v = *(const float2*)&V[(size_t)d * P_DIM + k];
    int nblk = d >> 7, n = d & 127;
    int c = ks / KSPC, ksl = ks % KSPC;
    g_Vb[(((size_t)(nblk * 3 + c) * 128 + n) * 88) + ksl * 8 + q] = packbf(v.x, v.y);
}

// ---------------- secant ----------------
__device__ __forceinline__ float secf(float x, float egz, float zp) {
    float t = 1.f - egz * expf(-GAMMA * x);
    return t * t * x - zp;
}

// ---------------- kernel B: per-row stats ----------------
__global__ __launch_bounds__(256) void k_rowstats(
    const float* __restrict__ Z_all, const float* __restrict__ U,
    const float* __restrict__ zmu, const int* __restrict__ choice, int N) {

    __shared__ float Zs[8][D_DIM];
    __shared__ float zmuS[D_DIM];
    __shared__ float xmuUS[K_DIM], xcUS[K_DIM];

    int tid = threadIdx.x;
    for (int d = tid; d < D_DIM; d += 256) zmuS[d] = zmu[d];
    if (tid < K_DIM) { xmuUS[tid] = g_xmuU[tid]; xcUS[tid] = g_xcU[tid]; }
    __syncthreads();

    int w = tid >> 5, lane = tid & 31;
    int n = blockIdx.x * 8 + w;
    if (n >= N) return;
    size_t row = (size_t)choice[n];

    const float4* Zrow = (const float4*)(Z_all + row * D_DIM);
    float4* Zs4 = (float4*)Zs[w];
    const float4* zmu4 = (const float4*)zmuS;

    float zn = 0.f;
    #pragma unroll
    for (int i = 0; i < 4; ++i) {
        int c4 = lane + 32 * i;
        float4 z = Zrow[c4];
        Zs4[c4] = z;
        float4 m = zmu4[c4];
        float dx = z.x - m.x, dy = z.y - m.y, dz = z.z - m.z, dw = z.w - m.w;
        zn += dx * dx + dy * dy + dz * dz + dw * dw;
    }
    __syncwarp();
    #pragma unroll
    for (int o = 16; o; o >>= 1) zn += __shfl_xor_sync(~0u, zn, o);

    int jq = lane & 7, dg = lane >> 3;
    const float4* U4 = (const float4*)U;
    float4 acc = make_float4(0.f, 0.f, 0.f, 0.f);
    #pragma unroll 4
    for (int d = dg; d < D_DIM; d += 4) {
        float4 u = U4[d * 8 + jq];
        float z = Zs[w][d];
        acc.x = fmaf(z, u.x, acc.x);
        acc.y = fmaf(z, u.y, acc.y);
        acc.z = fmaf(z, u.z, acc.z);
        acc.w = fmaf(z, u.w, acc.w);
    }
    #pragma unroll
    for (int o = 8; o <= 16; o <<= 1) {
        acc.x += __shfl_xor_sync(~0u, acc.x, o);
        acc.y += __shfl_xor_sync(~0u, acc.y, o);
        acc.z += __shfl_xor_sync(~0u, acc.z, o);
        acc.w += __shfl_xor_sync(~0u, acc.w, o);
    }

    float4 xm = ((const float4*)xmuUS)[jq];
    float dx = acc.x - xm.x, dy = acc.y - xm.y, dz = acc.z - xm.z, dw = acc.w - xm.w;
    float s = dx * dx + dy * dy + dz * dz + dw * dw;
    float zun = (dg == 0) ? s : 0.f;
    #pragma unroll
    for (int o = 16; o; o >>= 1) zun += __shfl_xor_sync(~0u, zun, o);

    if (dg == 0) {
        float4 xcv = ((const float4*)xcUS)[jq];
        ((float4*)(g_coord + (size_t)n * K_DIM))[jq] =
            make_float4(acc.x - xcv.x, acc.y - xcv.y, acc.z - xcv.z, acc.w - xcv.w);
    }

    if (lane == 0) {
        float zp = zn - zun;
        float egz = expf(-GAMMA * zun);
        float x_m2 = zp * GUESS_RATIO, x_m1 = zp;
        float f_m2 = secf(x_m2, egz, zp);
        for (int it = 0; it < 100; ++it) {
            float f_m1 = secf(x_m1, egz, zp);
            float fd = f_m1 - f_m2;
            if (fabsf(fd) < TOLF) fd = (fd >= 0.f) ? TOLF : -TOLF;
            float x = x_m1 - f_m1 * (x_m1 - x_m2) / fd;
            float st = fabsf(x - x_m1);
            x_m2 = x_m1; f_m2 = f_m1; x_m1 = x;
            if (st < TOLF) break;
        }
        g_kv[n] = expf(-GAMMA * (zun + x_m1));
    }
}

// ---------------- kernel C: HMMA GEMM + fused epilogue ----------------
// smem layout (bytes)
#define OFF_B   0               // 3*45056 = 135168
#define OFF_H   135168          // 2 * 128*32 = 8192
#define OFF_CRD 143360          // 128*33*4 = 16896
#define OFF_CHG 160256          // 128*4
#define OFF_KV  160768
#define OFF_CHC 161280
#define OFF_IUP 161792          // 528*2 u16
#define OFF_MB  162848          // 3 mbars
#define SMEM_SZ 163840

__global__ __launch_bounds__(256, 1) void k_gemm(
    const float* __restrict__ Z_all, const int* __restrict__ choice,
    float* __restrict__ out, int N) {

    extern __shared__ __align__(16) char smem[];
    uint32_t sb = smem_u32(smem);
    int tid = threadIdx.x;
    int m0 = blockIdx.x * MT;
    int d0 = blockIdx.y * 128;

    float* chgS = (float*)(smem + OFF_CHG);
    float* kvS  = (float*)(smem + OFF_KV);
    int*   chcS = (int*)(smem + OFF_CHC);
    uint16_t* iup = (uint16_t*)(smem + OFF_IUP);
    float* crdS = (float*)(smem + OFF_CRD);

    uint32_t mb[3] = {sb + OFF_MB, sb + OFF_MB + 8, sb + OFF_MB + 16};

    if (tid == 0) {
        MBAR_INIT(mb[0], 1);
        MBAR_INIT(mb[1], 1);
        MBAR_INIT(mb[2], 1);
        FENCE_ASYNC();
        int nblk = blockIdx.y;
        #pragma unroll
        for (int c = 0; c < 3; ++c) {
            MBAR_EXPECT_TX(mb[c], CHB);
            bulk_g2s(sb + OFF_B + c * CHB,
                     (const char*)g_Vb + ((size_t)nblk * 3 + c) * CHB, CHB, mb[c]);
        }
    }

    // smem init
    if (tid < K_DIM) {
        int i = tid;
        int off = i * K_DIM - (i * (i - 1)) / 2;
        for (int j = i; j < K_DIM; ++j)
            iup[off + j - i] = (uint16_t)(i | (j << 8));
    }
    if (tid < 128) {
        chgS[tid] = g_change[d0 + tid];
        int gm = m0 + tid;
        kvS[tid]  = (gm < N) ? g_kv[gm] : 0.f;
        chcS[tid] = (gm < N) ? choice[gm] : 0;
    }
    for (int e = tid; e < MT * 8; e += 256) {     // coord rows (row-major, pad 33)
        int m = e >> 3, q = e & 7;
        float4 v = ((const float4*)(g_coord + (size_t)(m0 + m) * K_DIM))[q];
        float* dst = &crdS[m * 33 + q * 4];
        dst[0] = v.x; dst[1] = v.y; dst[2] = v.z; dst[3] = v.w;
    }
    __syncthreads();

    int lane = tid & 31, wid = tid >> 5;
    int g = lane >> 2, i4 = lane & 3;
    int warp_m0 = (wid >> 1) * 32;
    int warp_n0 = (wid & 1) * 64;

    float acc[2][8][4] = {};

    // H generator (warps 0-3; one per SMSP): row m = tid
    const float* cm = &crdS[tid * 33];

    // gen step 0
    if (tid < 128) {
        uint32_t w[8];
        #pragma unroll
        for (int q = 0; q < 8; ++q) {
            int kb = 2 * (q >> 1) + 8 * (q & 1);
            uint32_t p0 = iup[kb], p1 = iup[kb + 1];
            w[q] = packbf(cm[p0 & 255] * cm[p0 >> 8], cm[p1 & 255] * cm[p1 >> 8]);
        }
        uint4* dst = (uint4*)(smem + OFF_H + tid * 32);
        dst[0] = make_uint4(w[0], w[1], w[2], w[3]);
        dst[1] = make_uint4(w[4], w[5], w[6], w[7]);
    }

    MBAR_WAIT(mb[0], 0);

    int c = 0, ksl = 0;
    #pragma unroll 1
    for (int ks = 0; ks < NKS; ++ks) {
        __syncthreads();
        // mma step: A from Hsm buf ks&1, B from chunk c
        const char* hb = smem + OFF_H + (ks & 1) * 4096 + i4 * 8;
        const char* bb = smem + OFF_B + c * CHB + ksl * 32 + i4 * 8;
        uint32_t a[2][4];
        #pragma unroll
        for (int mt = 0; mt < 2; ++mt) {
            int r = warp_m0 + mt * 16 + g;
            uint2 u = *(const uint2*)(hb + r * 32);
            uint2 v = *(const uint2*)(hb + (r + 8) * 32);
            a[mt][0] = u.x; a[mt][1] = v.x; a[mt][2] = u.y; a[mt][3] = v.y;
        }
        #pragma unroll
        for (int nt = 0; nt < 8; ++nt) {
            int n = warp_n0 + nt * 8 + g;
            uint2 b = *(const uint2*)(bb + n * 352);
            uint32_t br[2] = {b.x, b.y};
            mma16816(acc[0][nt], a[0], br);
            mma16816(acc[1][nt], a[1], br);
        }
        // generate H for step ks+1 into other buffer
        if (ks + 1 < NKS && tid < 128) {
            int kbase = (ks + 1) * 16;
            uint32_t w[8];
            #pragma unroll
            for (int q = 0; q < 8; ++q) {
                int kb = kbase + 2 * (q >> 1) + 8 * (q & 1);
                uint32_t p0 = iup[kb], p1 = iup[kb + 1];
                w[q] = packbf(cm[p0 & 255] * cm[p0 >> 8], cm[p1 & 255] * cm[p1 >> 8]);
            }
            uint4* dst = (uint4*)(smem + OFF_H + ((ks + 1) & 1) * 4096 + tid * 32);
            dst[0] = make_uint4(w[0], w[1], w[2], w[3]);
            dst[1] = make_uint4(w[4], w[5], w[6], w[7]);
        }
        if (++ksl == KSPC) {
            ksl = 0; ++c;
            if (c < 3) MBAR_WAIT(mb[c], 0);
        }
    }

    // epilogue: out[row][d] = Z[row][d] + kv*(chg + acc)
    #pragma unroll
    for (int mt = 0; mt < 2; ++mt) {
        #pragma unroll
        for (int rr = 0; rr < 2; ++rr) {
            int r = warp_m0 + mt * 16 + g + rr * 8;
            int gm = m0 + r;
            if (gm >= N) continue;
            float kv = kvS[r];
            size_t base = (size_t)chcS[r] * D_DIM + d0 + warp_n0 + 2 * i4;
            #pragma unroll
            for (int nt = 0; nt < 8; ++nt) {
                size_t idx = base + nt * 8;
                int nl = warp_n0 + nt * 8 + 2 * i4;
                float2 z = *(const float2*)&Z_all[idx];
                float2 o;
                o.x = z.x + kv * (chgS[nl]     + acc[mt][nt][rr * 2]);
                o.y = z.y + kv * (chgS[nl + 1] + acc[mt][nt][rr * 2 + 1]);
                *(float2*)&out[idx] = o;
            }
        }
    }
}

// ---------------- launch ----------------
extern "C" void kernel_launch(void* const* d_in, const int* in_sizes, int n_in,
                              void* d_out, int out_size) {
    const float* Z_all = (const float*)d_in[0];
    const float* U     = (const float*)d_in[1];
    const float* V     = (const float*)d_in[2];
    const float* zmu   = (const float*)d_in[3];
    const float* xc    = (const float*)d_in[4];
    const int*   choice= (const int*)d_in[5];
    int N = in_sizes[5];
    float* out = (float*)d_out;

    cudaFuncSetAttribute(k_gemm, cudaFuncAttributeMaxDynamicSharedMemorySize, SMEM_SZ);

    k_init<<<1, 512>>>(U, zmu, xc);
    k_prepV<<<dim3(2, 512), 132>>>(V);
    k_rowstats<<<(N + 7) / 8, 256>>>(Z_all, U, zmu, choice, N);
    cudaMemcpyAsync(d_out, d_in[0], (size_t)out_size * sizeof(float),
                    cudaMemcpyDeviceToDevice);
    dim3 grid((N + MT - 1) / MT, 4);
    k_gemm<<<grid, 256, SMEM_SZ>>>(Z_all, choice, out, N);
}

// round 8
// speedup vs baseline: 2.8693x; 1.3120x over previous
#include <cuda_runtime.h>
#include <cuda_bf16.h>
#include <cstdint>

#define D_DIM 512
#define K_DIM 32
#define P_DIM 528            // K*(K+1)/2 = 33*16
#define MAXN  100352
#define GAMMA 0.01f
#define TOLF  1e-6f
#define GUESS_RATIO (1.0f - 0.001f)

#define NKS   33             // k-steps of 16
#define GS    3              // k-steps per group
#define NG    11             // groups (NG*GS == NKS)
#define STB   4096           // bytes of B per k-step (128n * 8u32)
#define GB    (GS * STB)     // 12288 B per group
#define MT    128

// ---------------- device scratch ----------------
__device__ float g_coord[(size_t)MAXN * K_DIM];
__device__ float g_kv[MAXN];
__device__ uint32_t g_cover[MAXN / 32];
// B image: [4 nblk][11 grp][3 sl][128 n][8 u32]
__device__ __align__(16) uint32_t g_Vb[4 * NG * GS * 128 * 8];
__device__ float g_xmuU[K_DIM];
__device__ float g_xcU[K_DIM];
__device__ float g_change[D_DIM];

// ---------------- PTX helpers ----------------
__device__ __forceinline__ uint32_t smem_u32(const void* p) {
    uint32_t a;
    asm("{ .reg .u64 t; cvta.to.shared.u64 t, %1; cvt.u32.u64 %0, t; }" : "=r"(a) : "l"(p));
    return a;
}
#define MBAR_INIT(a, c) asm volatile("mbarrier.init.shared.b64 [%0], %1;" :: "r"(a), "r"(c) : "memory")
#define MBAR_EXPECT_TX(a, b) asm volatile("mbarrier.arrive.expect_tx.shared.b64 _, [%0], %1;" :: "r"(a), "r"(b) : "memory")
#define MBAR_WAIT(a, p) do { \
    uint32_t _m = (a), _p = (p), _d; \
    asm volatile("{ .reg .pred q; mbarrier.try_wait.parity.acquire.cta.shared::cta.b64 q, [%1], %2; selp.b32 %0,1,0,q; }" \
        : "=r"(_d) : "r"(_m), "r"(_p) : "memory"); \
    if (!_d) asm volatile("{ .reg .pred Q; WL%=: mbarrier.try_wait.parity.acquire.cta.shared::cta.b64 Q, [%0], %1, 0x989680; @Q bra.uni WD%=; bra.uni WL%=; WD%=: }" \
        :: "r"(_m), "r"(_p) : "memory"); \
} while (0)
#define FENCE_ASYNC() asm volatile("fence.proxy.async.shared::cta;" ::: "memory")

__device__ __forceinline__ void bulk_g2s(uint32_t dst, const void* src, uint32_t bytes, uint32_t mbar) {
    asm volatile("cp.async.bulk.shared::cta.global.mbarrier::complete_tx::bytes [%0], [%1], %2, [%3];"
        :: "r"(dst), "l"(src), "r"(bytes), "r"(mbar) : "memory");
}
__device__ __forceinline__ void mma16816(float* c, const uint32_t* a, const uint32_t* b) {
    asm volatile("mma.sync.aligned.m16n8k16.row.col.f32.bf16.bf16.f32 "
        "{%0,%1,%2,%3}, {%4,%5,%6,%7}, {%8,%9}, {%0,%1,%2,%3};"
        : "+f"(c[0]), "+f"(c[1]), "+f"(c[2]), "+f"(c[3])
        : "r"(a[0]), "r"(a[1]), "r"(a[2]), "r"(a[3]), "r"(b[0]), "r"(b[1]));
}
__device__ __forceinline__ uint32_t packbf(float a, float b) {
    __nv_bfloat162 r = __float22bfloat162_rn(make_float2(a, b));
    return *(uint32_t*)&r;
}

// ---------------- kernel A: small vectors + bitmap clear ----------------
__global__ void k_init(const float* __restrict__ U,
                       const float* __restrict__ zmu,
                       const float* __restrict__ xc) {
    __shared__ float s_xmuU[K_DIM], s_xcU[K_DIM];
    int t = threadIdx.x;
    for (int i = t; i < MAXN / 32; i += 512) g_cover[i] = 0u;
    if (t < 64) {
        int j = t & 31;
        bool is_mu = t < 32;
        const float* v = is_mu ? zmu : xc;
        float s = 0.f;
        for (int d = 0; d < D_DIM; ++d) s = fmaf(v[d], U[d * K_DIM + j], s);
        if (is_mu) { s_xmuU[j] = s; g_xmuU[j] = s; }
        else       { s_xcU[j]  = s; g_xcU[j]  = s; }
    }
    __syncthreads();
    for (int d = t; d < D_DIM; d += blockDim.x) {
        float s = 0.f;
        #pragma unroll
        for (int j = 0; j < K_DIM; ++j)
            s = fmaf(s_xcU[j] - s_xmuU[j], U[d * K_DIM + j], s);
        g_change[d] = xc[d] - zmu[d] - s;
    }
}

// ---------------- kernel P: build permuted bf16 B image ----------------
__global__ void k_prepV(const float* __restrict__ V) {
    int pos = threadIdx.x;                 // 0..263 valid
    if (pos >= 264) return;
    int d = blockIdx.x;
    int ks = pos >> 3, q = pos & 7;
    int k = ks * 16 + 2 * (q >> 1) + 8 * (q & 1);
    float2 v = *(const float2*)&V[(size_t)d * P_DIM + k];
    int nblk = d >> 7, n = d & 127;
    int grp = ks / GS, sl = ks % GS;
    g_Vb[((((size_t)(nblk * NG + grp) * GS + sl) * 128 + n) * 8) + q] = packbf(v.x, v.y);
}

// ---------------- secant ----------------
__device__ __forceinline__ float secf(float x, float egz, float zp) {
    float t = 1.f - egz * expf(-GAMMA * x);
    return t * t * x - zp;
}

// ---------------- kernel B: per-row stats ----------------
__global__ __launch_bounds__(256) void k_rowstats(
    const float* __restrict__ Z_all, const float* __restrict__ U,
    const float* __restrict__ zmu, const int* __restrict__ choice, int N) {

    __shared__ float Zs[8][D_DIM];
    __shared__ float zmuS[D_DIM];
    __shared__ float xmuUS[K_DIM], xcUS[K_DIM];

    int tid = threadIdx.x;
    for (int d = tid; d < D_DIM; d += 256) zmuS[d] = zmu[d];
    if (tid < K_DIM) { xmuUS[tid] = g_xmuU[tid]; xcUS[tid] = g_xcU[tid]; }
    __syncthreads();

    int w = tid >> 5, lane = tid & 31;
    int n = blockIdx.x * 8 + w;
    if (n >= N) return;
    int row = choice[n];

    const float4* Zrow = (const float4*)(Z_all + (size_t)row * D_DIM);
    float4* Zs4 = (float4*)Zs[w];
    const float4* zmu4 = (const float4*)zmuS;

    float zn = 0.f;
    #pragma unroll
    for (int i = 0; i < 4; ++i) {
        int c4 = lane + 32 * i;
        float4 z = Zrow[c4];
        Zs4[c4] = z;
        float4 m = zmu4[c4];
        float dx = z.x - m.x, dy = z.y - m.y, dz = z.z - m.z, dw = z.w - m.w;
        zn += dx * dx + dy * dy + dz * dz + dw * dw;
    }
    __syncwarp();
    #pragma unroll
    for (int o = 16; o; o >>= 1) zn += __shfl_xor_sync(~0u, zn, o);

    int jq = lane & 7, dg = lane >> 3;
    const float4* U4 = (const float4*)U;
    float4 acc = make_float4(0.f, 0.f, 0.f, 0.f);
    #pragma unroll 4
    for (int d = dg; d < D_DIM; d += 4) {
        float4 u = U4[d * 8 + jq];
        float z = Zs[w][d];
        acc.x = fmaf(z, u.x, acc.x);
        acc.y = fmaf(z, u.y, acc.y);
        acc.z = fmaf(z, u.z, acc.z);
        acc.w = fmaf(z, u.w, acc.w);
    }
    #pragma unroll
    for (int o = 8; o <= 16; o <<= 1) {
        acc.x += __shfl_xor_sync(~0u, acc.x, o);
        acc.y += __shfl_xor_sync(~0u, acc.y, o);
        acc.z += __shfl_xor_sync(~0u, acc.z, o);
        acc.w += __shfl_xor_sync(~0u, acc.w, o);
    }

    float4 xm = ((const float4*)xmuUS)[jq];
    float dx = acc.x - xm.x, dy = acc.y - xm.y, dz = acc.z - xm.z, dw = acc.w - xm.w;
    float s = dx * dx + dy * dy + dz * dz + dw * dw;
    float zun = (dg == 0) ? s : 0.f;
    #pragma unroll
    for (int o = 16; o; o >>= 1) zun += __shfl_xor_sync(~0u, zun, o);

    if (dg == 0) {
        float4 xcv = ((const float4*)xcUS)[jq];
        ((float4*)(g_coord + (size_t)n * K_DIM))[jq] =
            make_float4(acc.x - xcv.x, acc.y - xcv.y, acc.z - xcv.z, acc.w - xcv.w);
    }

    if (lane == 0) {
        atomicOr(&g_cover[row >> 5], 1u << (row & 31));
        float zp = zn - zun;
        float egz = expf(-GAMMA * zun);
        float x_m2 = zp * GUESS_RATIO, x_m1 = zp;
        float f_m2 = secf(x_m2, egz, zp);
        for (int it = 0; it < 100; ++it) {
            float f_m1 = secf(x_m1, egz, zp);
            float fd = f_m1 - f_m2;
            if (fabsf(fd) < TOLF) fd = (fd >= 0.f) ? TOLF : -TOLF;
            float x = x_m1 - f_m1 * (x_m1 - x_m2) / fd;
            float st = fabsf(x - x_m1);
            x_m2 = x_m1; f_m2 = f_m1; x_m1 = x;
            if (st < 3e-6f * fabsf(x) + TOLF) break;   // fp32-noise-aware stop
        }
        g_kv[n] = expf(-GAMMA * (zun + x_m1));
    }
}

// ---------------- kernel F: copy uncovered rows ----------------
__global__ __launch_bounds__(256) void k_fill(const float* __restrict__ Z_all,
                                              float* __restrict__ out, int rows) {
    int r = blockIdx.x * 8 + (threadIdx.x >> 5);
    if (r >= rows) return;
    if (g_cover[r >> 5] & (1u << (r & 31))) return;
    int lane = threadIdx.x & 31;
    const float4* z = (const float4*)(Z_all + (size_t)r * D_DIM);
    float4* o = (float4*)(out + (size_t)r * D_DIM);
    #pragma unroll
    for (int i = 0; i < 4; ++i) o[lane + 32 * i] = z[lane + 32 * i];
}

// ---------------- kernel C: HMMA GEMM + fused epilogue ----------------
// smem (bytes): B ring 4*12288=49152 | H 2*12288=24576 | crd 16896 | misc
#define OFF_B   0
#define OFF_H   49152
#define OFF_CRD 73728
#define OFF_CHG 90624
#define OFF_KV  91136
#define OFF_CHC 91648
#define OFF_IUP 92160
#define OFF_MB  93248
#define SMEM_SZ 93440

__global__ __launch_bounds__(256, 2) void k_gemm(
    const float* __restrict__ Z_all, const int* __restrict__ choice,
    float* __restrict__ out, int N) {

    extern __shared__ __align__(16) char smem[];
    uint32_t sb = smem_u32(smem);
    int tid = threadIdx.x;
    int m0 = blockIdx.x * MT;
    int d0 = blockIdx.y * 128;

    float* chgS = (float*)(smem + OFF_CHG);
    float* kvS  = (float*)(smem + OFF_KV);
    int*   chcS = (int*)(smem + OFF_CHC);
    uint16_t* iup = (uint16_t*)(smem + OFF_IUP);
    float* crdS = (float*)(smem + OFF_CRD);

    uint32_t mb[4] = {sb + OFF_MB, sb + OFF_MB + 8, sb + OFF_MB + 16, sb + OFF_MB + 24};
    const char* Vbase = (const char*)g_Vb + (size_t)blockIdx.y * NG * GB;

    if (tid == 0) {
        #pragma unroll
        for (int s = 0; s < 4; ++s) MBAR_INIT(mb[s], 1);
        FENCE_ASYNC();
        #pragma unroll
        for (int gq = 0; gq < 3; ++gq) {
            MBAR_EXPECT_TX(mb[gq], GB);
            bulk_g2s(sb + OFF_B + gq * GB, Vbase + (size_t)gq * GB, GB, mb[gq]);
        }
    }

    // smem init
    if (tid < K_DIM) {
        int i = tid;
        int off = i * K_DIM - (i * (i - 1)) / 2;
        for (int j = i; j < K_DIM; ++j)
            iup[off + j - i] = (uint16_t)(i | (j << 8));
    }
    if (tid < 128) {
        chgS[tid] = g_change[d0 + tid];
        int gm = m0 + tid;
        kvS[tid]  = (gm < N) ? g_kv[gm] : 0.f;
        chcS[tid] = (gm < N) ? choice[gm] : 0;
    }
    for (int e = tid; e < MT * 8; e += 256) {
        int m = e >> 3, q = e & 7;
        float4 v = ((const float4*)(g_coord + (size_t)(m0 + m) * K_DIM))[q];
        float* dst = &crdS[m * 33 + q * 4];
        dst[0] = v.x; dst[1] = v.y; dst[2] = v.z; dst[3] = v.w;
    }
    __syncthreads();

    int lane = tid & 31, wid = tid >> 5;
    int gl = lane >> 2, i4 = lane & 3;
    int warp_m0 = (wid >> 1) * 32;
    int warp_n0 = (wid & 1) * 64;

    float acc[2][8][4] = {};

    // H generator: thread -> row m = tid>>1, half h = tid&1
    int gm_row = tid >> 1, gh = tid & 1;
    const float* cm = &crdS[gm_row * 33];

    // gen group 0 into buffer 0
    #pragma unroll
    for (int sl = 0; sl < GS; ++sl) {
        int kbase = sl * 16;
        uint32_t w[4];
        #pragma unroll
        for (int qq = 0; qq < 4; ++qq) {
            int q = gh * 4 + qq;
            int kb = kbase + 2 * (q >> 1) + 8 * (q & 1);
            uint32_t p0 = iup[kb], p1 = iup[kb + 1];
            w[qq] = packbf(cm[p0 & 255] * cm[p0 >> 8], cm[p1 & 255] * cm[p1 >> 8]);
        }
        *(uint4*)(smem + OFF_H + sl * STB + gm_row * 32 + gh * 16) =
            make_uint4(w[0], w[1], w[2], w[3]);
    }

    #pragma unroll 1
    for (int g = 0; g < NG; ++g) {
        __syncthreads();
        if (tid == 0 && g + 3 < NG) {
            int slot = (g + 3) & 3;
            MBAR_EXPECT_TX(mb[slot], GB);
            bulk_g2s(sb + OFF_B + slot * GB, Vbase + (size_t)(g + 3) * GB, GB, mb[slot]);
        }
        MBAR_WAIT(mb[g & 3], (g >> 2) & 1);

        const char* hbuf = smem + OFF_H + (g & 1) * GB;
        const char* bbuf = smem + OFF_B + (g & 3) * GB;
        #pragma unroll
        for (int sl = 0; sl < GS; ++sl) {
            const char* hb = hbuf + sl * STB + i4 * 8;
            const char* bb = bbuf + sl * STB + i4 * 8;
            uint32_t a[2][4];
            #pragma unroll
            for (int mt = 0; mt < 2; ++mt) {
                int r = warp_m0 + mt * 16 + gl;
                uint2 u = *(const uint2*)(hb + r * 32);
                uint2 v = *(const uint2*)(hb + (r + 8) * 32);
                a[mt][0] = u.x; a[mt][1] = v.x; a[mt][2] = u.y; a[mt][3] = v.y;
            }
            #pragma unroll
            for (int nt = 0; nt < 8; ++nt) {
                int n = warp_n0 + nt * 8 + gl;
                uint2 b = *(const uint2*)(bb + n * 32);
                uint32_t br[2] = {b.x, b.y};
                mma16816(acc[0][nt], a[0], br);
                mma16816(acc[1][nt], a[1], br);
            }
        }
        // generate H for group g+1 into other buffer
        if (g + 1 < NG) {
            #pragma unroll
            for (int sl = 0; sl < GS; ++sl) {
                int kbase = ((g + 1) * GS + sl) * 16;
                uint32_t w[4];
                #pragma unroll
                for (int qq = 0; qq < 4; ++qq) {
                    int q = gh * 4 + qq;
                    int kb = kbase + 2 * (q >> 1) + 8 * (q & 1);
                    uint32_t p0 = iup[kb], p1 = iup[kb + 1];
                    w[qq] = packbf(cm[p0 & 255] * cm[p0 >> 8], cm[p1 & 255] * cm[p1 >> 8]);
                }
                *(uint4*)(smem + OFF_H + ((g + 1) & 1) * GB + sl * STB + gm_row * 32 + gh * 16) =
                    make_uint4(w[0], w[1], w[2], w[3]);
            }
        }
    }

    // epilogue
    #pragma unroll
    for (int mt = 0; mt < 2; ++mt) {
        #pragma unroll
        for (int rr = 0; rr < 2; ++rr) {
            int r = warp_m0 + mt * 16 + gl + rr * 8;
            int gm = m0 + r;
            if (gm >= N) continue;
            float kv = kvS[r];
            size_t base = (size_t)chcS[r] * D_DIM + d0 + warp_n0 + 2 * i4;
            #pragma unroll
            for (int nt = 0; nt < 8; ++nt) {
                size_t idx = base + nt * 8;
                int nl = warp_n0 + nt * 8 + 2 * i4;
                float2 z = *(const float2*)&Z_all[idx];
                float2 o;
                o.x = z.x + kv * (chgS[nl]     + acc[mt][nt][rr * 2]);
                o.y = z.y + kv * (chgS[nl + 1] + acc[mt][nt][rr * 2 + 1]);
                *(float2*)&out[idx] = o;
            }
        }
    }
}

// ---------------- launch ----------------
extern "C" void kernel_launch(void* const* d_in, const int* in_sizes, int n_in,
                              void* d_out, int out_size) {
    const float* Z_all = (const float*)d_in[0];
    const float* U     = (const float*)d_in[1];
    const float* V     = (const float*)d_in[2];
    const float* zmu   = (const float*)d_in[3];
    const float* xc    = (const float*)d_in[4];
    const int*   choice= (const int*)d_in[5];
    int N = in_sizes[5];
    float* out = (float*)d_out;
    int rows = out_size / D_DIM;

    cudaFuncSetAttribute(k_gemm, cudaFuncAttributeMaxDynamicSharedMemorySize, SMEM_SZ);

    k_init<<<1, 512>>>(U, zmu, xc);
    k_prepV<<<512, 288>>>(V);
    k_rowstats<<<(N + 7) / 8, 256>>>(Z_all, U, zmu, choice, N);
    k_fill<<<(rows + 7) / 8, 256>>>(Z_all, out, rows);
    dim3 grid((N + MT - 1) / MT, 4);
    k_gemm<<<grid, 256, SMEM_SZ>>>(Z_all, choice, out, N);
}

// round 12
// speedup vs baseline: 3.8493x; 1.3416x over previous
#include <cuda_runtime.h>
#include <cuda_bf16.h>
#include <cstdint>

#define D_DIM 512
#define K_DIM 32
#define P_DIM 528            // K*(K+1)/2 = 33*16
#define MAXN  100352
#define GAMMA 0.01f
#define TOLF  1e-6f
#define GUESS_RATIO (1.0f - 0.001f)

#define NKS   33             // k-steps of 16
#define GS    3              // k-steps per group
#define NG    11             // groups (NG*GS == NKS)
#define STB   4096           // bytes of B per k-step (128n * 8u32)
#define GB    (GS * STB)     // 12288 B per group
#define MT    128

// ---------------- device scratch ----------------
__device__ float g_coord[(size_t)MAXN * K_DIM];
__device__ float g_kv[MAXN];
__device__ float2 g_norms[MAXN];
__device__ uint32_t g_cover[MAXN / 32];
// B image for big gemm: [4 nblk][11 grp][3 sl][128 n][8 u32]
__device__ __align__(16) uint32_t g_Vb[4 * NG * GS * 128 * 8];
// U image for rowstats: [32 ks][32 j][8 u32]
__device__ __align__(16) uint32_t g_Ub[32 * 32 * 8];
__device__ float g_xmuU[K_DIM];
__device__ float g_xcU[K_DIM];
__device__ float g_dU[K_DIM];            // xmuU - xcU
__device__ float g_change[D_DIM];

// ---------------- PTX helpers ----------------
__device__ __forceinline__ uint32_t smem_u32(const void* p) {
    uint32_t a;
    asm("{ .reg .u64 t; cvta.to.shared.u64 t, %1; cvt.u32.u64 %0, t; }" : "=r"(a) : "l"(p));
    return a;
}
#define MBAR_INIT(a, c) asm volatile("mbarrier.init.shared.b64 [%0], %1;" :: "r"(a), "r"(c) : "memory")
#define MBAR_EXPECT_TX(a, b) asm volatile("mbarrier.arrive.expect_tx.shared.b64 _, [%0], %1;" :: "r"(a), "r"(b) : "memory")
#define MBAR_WAIT(a, p) do { \
    uint32_t _m = (a), _p = (p), _d; \
    asm volatile("{ .reg .pred q; mbarrier.try_wait.parity.acquire.cta.shared::cta.b64 q, [%1], %2; selp.b32 %0,1,0,q; }" \
        : "=r"(_d) : "r"(_m), "r"(_p) : "memory"); \
    if (!_d) asm volatile("{ .reg .pred Q; WL%=: mbarrier.try_wait.parity.acquire.cta.shared::cta.b64 Q, [%0], %1, 0x989680; @Q bra.uni WD%=; bra.uni WL%=; WD%=: }" \
        :: "r"(_m), "r"(_p) : "memory"); \
} while (0)
#define FENCE_ASYNC() asm volatile("fence.proxy.async.shared::cta;" ::: "memory")

__device__ __forceinline__ void bulk_g2s(uint32_t dst, const void* src, uint32_t bytes, uint32_t mbar) {
    asm volatile("cp.async.bulk.shared::cta.global.mbarrier::complete_tx::bytes [%0], [%1], %2, [%3];"
        :: "r"(dst), "l"(src), "r"(bytes), "r"(mbar) : "memory");
}
__device__ __forceinline__ void mma16816(float* c, const uint32_t* a, const uint32_t* b) {
    asm volatile("mma.sync.aligned.m16n8k16.row.col.f32.bf16.bf16.f32 "
        "{%0,%1,%2,%3}, {%4,%5,%6,%7}, {%8,%9}, {%0,%1,%2,%3};"
        : "+f"(c[0]), "+f"(c[1]), "+f"(c[2]), "+f"(c[3])
        : "r"(a[0]), "r"(a[1]), "r"(a[2]), "r"(a[3]), "r"(b[0]), "r"(b[1]));
}
__device__ __forceinline__ uint32_t packbf(float a, float b) {
    __nv_bfloat162 r = __float22bfloat162_rn(make_float2(a, b));
    return *(uint32_t*)&r;
}

// ---------------- kernel A: small vectors + bitmap clear ----------------
__global__ void k_init(const float* __restrict__ U,
                       const float* __restrict__ zmu,
                       const float* __restrict__ xc) {
    __shared__ float s_xmuU[K_DIM], s_xcU[K_DIM];
    int t = threadIdx.x;
    for (int i = t; i < MAXN / 32; i += 512) g_cover[i] = 0u;
    if (t < 64) {
        int j = t & 31;
        bool is_mu = t < 32;
        const float* v = is_mu ? zmu : xc;
        float s = 0.f;
        for (int d = 0; d < D_DIM; ++d) s = fmaf(v[d], U[d * K_DIM + j], s);
        if (is_mu) { s_xmuU[j] = s; g_xmuU[j] = s; }
        else       { s_xcU[j]  = s; g_xcU[j]  = s; }
    }
    __syncthreads();
    if (t < 32) g_dU[t] = s_xmuU[t] - s_xcU[t];
    for (int d = t; d < D_DIM; d += blockDim.x) {
        float s = 0.f;
        #pragma unroll
        for (int j = 0; j < K_DIM; ++j)
            s = fmaf(s_xcU[j] - s_xmuU[j], U[d * K_DIM + j], s);
        g_change[d] = xc[d] - zmu[d] - s;
    }
}

// ---------------- kernel P: permuted bf16 V image ----------------
__global__ void k_prepV(const float* __restrict__ V) {
    int pos = threadIdx.x;
    if (pos >= 264) return;
    int d = blockIdx.x;
    int ks = pos >> 3, q = pos & 7;
    int k = ks * 16 + 2 * (q >> 1) + 8 * (q & 1);
    float2 v = *(const float2*)&V[(size_t)d * P_DIM + k];
    int nblk = d >> 7, n = d & 127;
    int grp = ks / GS, sl = ks % GS;
    g_Vb[((((size_t)(nblk * NG + grp) * GS + sl) * 128 + n) * 8) + q] = packbf(v.x, v.y);
}

// ---------------- kernel PU: permuted bf16 U image ----------------
__global__ void k_prepU(const float* __restrict__ U) {
    int idx = blockIdx.x * 256 + threadIdx.x;    // 0..8191
    if (idx >= 8192) return;
    int q = idx & 7, j = (idx >> 3) & 31, ks = idx >> 8;
    int d = ks * 16 + 2 * (q >> 1) + 8 * (q & 1);
    g_Ub[idx] = packbf(U[d * K_DIM + j], U[(d + 1) * K_DIM + j]);
}

// ---------------- kernel B: per-row stats via HMMA ----------------
#define RS_A0   0
#define RS_A1   33024
#define RS_U    66048
#define RS_ZMU  98816
#define RS_DU   100864
#define RS_ZN   100992
#define RS_CHC  101504
#define RS_SMEM 102016
#define KSTRIDE 4128          // bytes per k-step in A tile (128 rows * 32B + 32 pad)

__global__ __launch_bounds__(256, 2) void k_rowstats(
    const float* __restrict__ Z_all, const float* __restrict__ zmu,
    const int* __restrict__ choice, int N) {

    extern __shared__ __align__(16) char rsm[];
    int tid = threadIdx.x;
    int lane = tid & 31, w = tid >> 5;
    int gl = lane >> 2, i4 = lane & 3;
    int n0 = blockIdx.x * 128;

    float* zmuS = (float*)(rsm + RS_ZMU);
    float* dUs  = (float*)(rsm + RS_DU);
    float* s_zn = (float*)(rsm + RS_ZN);
    int*   chcS = (int*)(rsm + RS_CHC);

    for (int i = tid; i < 512; i += 256) zmuS[i] = zmu[i];
    if (tid < 32) dUs[tid] = g_dU[tid];
    for (int e = tid; e < 2048; e += 256)
        ((uint4*)(rsm + RS_U))[e] = ((const uint4*)g_Ub)[e];
    if (tid < 128) chcS[tid] = choice[min(n0 + tid, N - 1)];
    __syncthreads();

    float acc[4][4] = {};
    float znp[16] = {};

    // conv(c): load Z chunk, subtract zmu, accumulate zn, pack bf16 A-frags
    auto conv = [&](int c) {
        char* Ad = rsm + ((c & 1) ? RS_A1 : RS_A0);
        #pragma unroll
        for (int i = 0; i < 16; ++i) {
            int e = tid + 256 * i;
            int row = e >> 5, col4 = e & 31;
            int d = c * 128 + col4 * 4;
            float4 z = *(const float4*)&Z_all[(size_t)chcS[row] * D_DIM + d];
            float4 m = *(const float4*)&zmuS[d];
            float z0 = z.x - m.x, z1 = z.y - m.y, z2 = z.z - m.z, z3 = z.w - m.w;
            znp[i] += z0 * z0 + z1 * z1 + z2 * z2 + z3 * z3;
            int ks = col4 >> 2, kb = (col4 & 3) * 4;
            int q0 = (kb & 6) + (kb >> 3);
            int q1 = ((kb + 2) & 6) + ((kb + 2) >> 3);
            uint32_t* A = (uint32_t*)(Ad + ks * KSTRIDE) + row * 8;
            A[q0] = packbf(z0, z1);
            A[q1] = packbf(z2, z3);
        }
    };

    conv(0);
    __syncthreads();
    #pragma unroll 1
    for (int c = 0; c < 4; ++c) {
        // mma chunk c
        const char* Ab = rsm + ((c & 1) ? RS_A1 : RS_A0);
        #pragma unroll
        for (int ks = 0; ks < 8; ++ks) {
            const char* hb = Ab + ks * KSTRIDE + i4 * 8;
            int r = w * 16 + gl;
            uint2 u = *(const uint2*)(hb + r * 32);
            uint2 v = *(const uint2*)(hb + (r + 8) * 32);
            uint32_t a[4] = {u.x, v.x, u.y, v.y};
            const char* bb = rsm + RS_U + (c * 8 + ks) * 1024 + i4 * 8;
            #pragma unroll
            for (int nt = 0; nt < 4; ++nt) {
                uint2 b = *(const uint2*)(bb + (nt * 8 + gl) * 32);
                uint32_t br[2] = {b.x, b.y};
                mma16816(acc[nt], a, br);
            }
        }
        if (c + 1 < 4) conv(c + 1);
        __syncthreads();
    }

    // zn reduce: warp w holds rows w + 8i in znp[i]
    #pragma unroll
    for (int i = 0; i < 16; ++i) {
        float v = znp[i];
        #pragma unroll
        for (int o = 16; o; o >>= 1) v += __shfl_xor_sync(~0u, v, o);
        if (lane == 0) s_zn[w + 8 * i] = v;
    }
    __syncthreads();

    // zun + coord from accumulators; acc = ZU - xmuU
    {
        int r0 = w * 16 + gl, r1 = r0 + 8;
        float zun0 = 0.f, zun1 = 0.f;
        #pragma unroll
        for (int nt = 0; nt < 4; ++nt) {
            zun0 += acc[nt][0] * acc[nt][0] + acc[nt][1] * acc[nt][1];
            zun1 += acc[nt][2] * acc[nt][2] + acc[nt][3] * acc[nt][3];
        }
        zun0 += __shfl_xor_sync(~0u, zun0, 1); zun0 += __shfl_xor_sync(~0u, zun0, 2);
        zun1 += __shfl_xor_sync(~0u, zun1, 1); zun1 += __shfl_xor_sync(~0u, zun1, 2);
        #pragma unroll
        for (int nt = 0; nt < 4; ++nt) {
            int cc = nt * 8 + 2 * i4;
            *(float2*)&g_coord[(size_t)(n0 + r0) * K_DIM + cc] =
                make_float2(acc[nt][0] + dUs[cc], acc[nt][1] + dUs[cc + 1]);
            *(float2*)&g_coord[(size_t)(n0 + r1) * K_DIM + cc] =
                make_float2(acc[nt][2] + dUs[cc], acc[nt][3] + dUs[cc + 1]);
        }
        if (i4 == 0) {
            g_norms[n0 + r0] = make_float2(s_zn[r0], zun0);
            g_norms[n0 + r1] = make_float2(s_zn[r1], zun1);
        }
    }
}

// ---------------- secant ----------------
__device__ __forceinline__ float secf(float x, float egz, float zp) {
    float t = 1.f - egz * expf(-GAMMA * x);
    return t * t * x - zp;
}

// ---------------- kernel S: parallel secant + cover bitmap ----------------
__global__ __launch_bounds__(256) void k_secant(const int* __restrict__ choice, int N) {
    int n = blockIdx.x * 256 + threadIdx.x;
    if (n >= N) return;
    int row = choice[n];
    atomicOr(&g_cover[row >> 5], 1u << (row & 31));
    float2 nm = g_norms[n];
    float zn = nm.x, zun = nm.y;
    float zp = zn - zun;
    float egz = expf(-GAMMA * zun);
    float x_m2 = zp * GUESS_RATIO, x_m1 = zp;
    float f_m2 = secf(x_m2, egz, zp);
    for (int it = 0; it < 100; ++it) {
        float f_m1 = secf(x_m1, egz, zp);
        float fd = f_m1 - f_m2;
        if (fabsf(fd) < TOLF) fd = (fd >= 0.f) ? TOLF : -TOLF;
        float x = x_m1 - f_m1 * (x_m1 - x_m2) / fd;
        float st = fabsf(x - x_m1);
        x_m2 = x_m1; f_m2 = f_m1; x_m1 = x;
        if (st < 3e-6f * fabsf(x) + TOLF) break;
    }
    g_kv[n] = expf(-GAMMA * (zun + x_m1));
}

// ---------------- kernel F: copy uncovered rows (warp-ballot) ----------------
__global__ __launch_bounds__(256) void k_fill(const float* __restrict__ Z_all,
                                              float* __restrict__ out, int rows) {
    int wi = (blockIdx.x * 256 + threadIdx.x) >> 5;
    int lane = threadIdx.x & 31;
    int r0 = wi * 32;
    if (r0 >= rows) return;
    uint32_t need = ~g_cover[wi];
    if (r0 + 32 > rows) need &= (1u << (rows - r0)) - 1u;
    while (need) {
        int b = __ffs(need) - 1;
        need &= need - 1;
        size_t r = (size_t)(r0 + b);
        const float4* z = (const float4*)(Z_all + r * D_DIM);
        float4* o = (float4*)(out + r * D_DIM);
        #pragma unroll
        for (int i = 0; i < 4; ++i) o[lane + 32 * i] = z[lane + 32 * i];
    }
}

// ---------------- kernel C: HMMA GEMM + fused epilogue (unchanged R8) ----------------
#define OFF_B   0
#define OFF_H   49152
#define OFF_CRD 73728
#define OFF_CHG 90624
#define OFF_KV  91136
#define OFF_CHC 91648
#define OFF_IUP 92160
#define OFF_MB  93248
#define SMEM_SZ 93440

__global__ __launch_bounds__(256, 2) void k_gemm(
    const float* __restrict__ Z_all, const int* __restrict__ choice,
    float* __restrict__ out, int N) {

    extern __shared__ __align__(16) char smem[];
    uint32_t sb = smem_u32(smem);
    int tid = threadIdx.x;
    int m0 = blockIdx.x * MT;
    int d0 = blockIdx.y * 128;

    float* chgS = (float*)(smem + OFF_CHG);
    float* kvS  = (float*)(smem + OFF_KV);
    int*   chcS = (int*)(smem + OFF_CHC);
    uint16_t* iup = (uint16_t*)(smem + OFF_IUP);
    float* crdS = (float*)(smem + OFF_CRD);

    uint32_t mb[4] = {sb + OFF_MB, sb + OFF_MB + 8, sb + OFF_MB + 16, sb + OFF_MB + 24};
    const char* Vbase = (const char*)g_Vb + (size_t)blockIdx.y * NG * GB;

    if (tid == 0) {
        #pragma unroll
        for (int s = 0; s < 4; ++s) MBAR_INIT(mb[s], 1);
        FENCE_ASYNC();
        #pragma unroll
        for (int gq = 0; gq < 3; ++gq) {
            MBAR_EXPECT_TX(mb[gq], GB);
            bulk_g2s(sb + OFF_B + gq * GB, Vbase + (size_t)gq * GB, GB, mb[gq]);
        }
    }

    if (tid < K_DIM) {
        int i = tid;
        int off = i * K_DIM - (i * (i - 1)) / 2;
        for (int j = i; j < K_DIM; ++j)
            iup[off + j - i] = (uint16_t)(i | (j << 8));
    }
    if (tid < 128) {
        chgS[tid] = g_change[d0 + tid];
        int gm = m0 + tid;
        kvS[tid]  = (gm < N) ? g_kv[gm] : 0.f;
        chcS[tid] = (gm < N) ? choice[gm] : 0;
    }
    for (int e = tid; e < MT * 8; e += 256) {
        int m = e >> 3, q = e & 7;
        float4 v = ((const float4*)(g_coord + (size_t)(m0 + m) * K_DIM))[q];
        float* dst = &crdS[m * 33 + q * 4];
        dst[0] = v.x; dst[1] = v.y; dst[2] = v.z; dst[3] = v.w;
    }
    __syncthreads();

    int lane = tid & 31, wid = tid >> 5;
    int gl = lane >> 2, i4 = lane & 3;
    int warp_m0 = (wid >> 1) * 32;
    int warp_n0 = (wid & 1) * 64;

    float acc[2][8][4] = {};

    int gm_row = tid >> 1, gh = tid & 1;
    const float* cm = &crdS[gm_row * 33];

    #pragma unroll
    for (int sl = 0; sl < GS; ++sl) {
        int kbase = sl * 16;
        uint32_t w[4];
        #pragma unroll
        for (int qq = 0; qq < 4; ++qq) {
            int q = gh * 4 + qq;
            int kb = kbase + 2 * (q >> 1) + 8 * (q & 1);
            uint32_t p0 = iup[kb], p1 = iup[kb + 1];
            w[qq] = packbf(cm[p0 & 255] * cm[p0 >> 8], cm[p1 & 255] * cm[p1 >> 8]);
        }
        *(uint4*)(smem + OFF_H + sl * STB + gm_row * 32 + gh * 16) =
            make_uint4(w[0], w[1], w[2], w[3]);
    }

    #pragma unroll 1
    for (int g = 0; g < NG; ++g) {
        __syncthreads();
        if (tid == 0 && g + 3 < NG) {
            int slot = (g + 3) & 3;
            MBAR_EXPECT_TX(mb[slot], GB);
            bulk_g2s(sb + OFF_B + slot * GB, Vbase + (size_t)(g + 3) * GB, GB, mb[slot]);
        }
        MBAR_WAIT(mb[g & 3], (g >> 2) & 1);

        const char* hbuf = smem + OFF_H + (g & 1) * GB;
        const char* bbuf = smem + OFF_B + (g & 3) * GB;
        #pragma unroll
        for (int sl = 0; sl < GS; ++sl) {
            const char* hb = hbuf + sl * STB + i4 * 8;
            const char* bb = bbuf + sl * STB + i4 * 8;
            uint32_t a[2][4];
            #pragma unroll
            for (int mt = 0; mt < 2; ++mt) {
                int r = warp_m0 + mt * 16 + gl;
                uint2 u = *(const uint2*)(hb + r * 32);
                uint2 v = *(const uint2*)(hb + (r + 8) * 32);
                a[mt][0] = u.x; a[mt][1] = v.x; a[mt][2] = u.y; a[mt][3] = v.y;
            }
            #pragma unroll
            for (int nt = 0; nt < 8; ++nt) {
                int n = warp_n0 + nt * 8 + gl;
                uint2 b = *(const uint2*)(bb + n * 32);
                uint32_t br[2] = {b.x, b.y};
                mma16816(acc[0][nt], a[0], br);
                mma16816(acc[1][nt], a[1], br);
            }
        }
        if (g + 1 < NG) {
            #pragma unroll
            for (int sl = 0; sl < GS; ++sl) {
                int kbase = ((g + 1) * GS + sl) * 16;
                uint32_t w[4];
                #pragma unroll
                for (int qq = 0; qq < 4; ++qq) {
                    int q = gh * 4 + qq;
                    int kb = kbase + 2 * (q >> 1) + 8 * (q & 1);
                    uint32_t p0 = iup[kb], p1 = iup[kb + 1];
                    w[qq] = packbf(cm[p0 & 255] * cm[p0 >> 8], cm[p1 & 255] * cm[p1 >> 8]);
                }
                *(uint4*)(smem + OFF_H + ((g + 1) & 1) * GB + sl * STB + gm_row * 32 + gh * 16) =
                    make_uint4(w[0], w[1], w[2], w[3]);
            }
        }
    }

    #pragma unroll
    for (int mt = 0; mt < 2; ++mt) {
        #pragma unroll
        for (int rr = 0; rr < 2; ++rr) {
            int r = warp_m0 + mt * 16 + gl + rr * 8;
            int gm = m0 + r;
            if (gm >= N) continue;
            float kv = kvS[r];
            size_t base = (size_t)chcS[r] * D_DIM + d0 + warp_n0 + 2 * i4;
            #pragma unroll
            for (int nt = 0; nt < 8; ++nt) {
                size_t idx = base + nt * 8;
                int nl = warp_n0 + nt * 8 + 2 * i4;
                float2 z = *(const float2*)&Z_all[idx];
                float2 o;
                o.x = z.x + kv * (chgS[nl]     + acc[mt][nt][rr * 2]);
                o.y = z.y + kv * (chgS[nl + 1] + acc[mt][nt][rr * 2 + 1]);
                *(float2*)&out[idx] = o;
            }
        }
    }
}

// ---------------- launch ----------------
extern "C" void kernel_launch(void* const* d_in, const int* in_sizes, int n_in,
                              void* d_out, int out_size) {
    const float* Z_all = (const float*)d_in[0];
    const float* U     = (const float*)d_in[1];
    const float* V     = (const float*)d_in[2];
    const float* zmu   = (const float*)d_in[3];
    const float* xc    = (const float*)d_in[4];
    const int*   choice= (const int*)d_in[5];
    int N = in_sizes[5];
    float* out = (float*)d_out;
    int rows = out_size / D_DIM;

    cudaFuncSetAttribute(k_gemm, cudaFuncAttributeMaxDynamicSharedMemorySize, SMEM_SZ);
    cudaFuncSetAttribute(k_rowstats, cudaFuncAttributeMaxDynamicSharedMemorySize, RS_SMEM);

    k_init<<<1, 512>>>(U, zmu, xc);
    k_prepV<<<512, 288>>>(V);
    k_prepU<<<32, 256>>>(U);
    k_rowstats<<<(N + 127) / 128, 256, RS_SMEM>>>(Z_all, zmu, choice, N);
    k_secant<<<(N + 255) / 256, 256>>>(choice, N);
    k_fill<<<(rows + 255) / 256, 256>>>(Z_all, out, rows);
    dim3 grid((N + MT - 1) / MT, 4);
    k_gemm<<<grid, 256, SMEM_SZ>>>(Z_all, choice, out, N);
}

// round 15
// speedup vs baseline: 4.3901x; 1.1405x over previous
#include <cuda_runtime.h>
#include <cuda_bf16.h>
#include <cstdint>

#define D_DIM 512
#define K_DIM 32
#define P_DIM 528            // K*(K+1)/2 = 33*16
#define MAXN  100352
#define GAMMA 0.01f
#define TOLF  1e-6f
#define GUESS_RATIO (1.0f - 0.001f)

#define NKS   33             // k-steps of 16
#define GS    3              // k-steps per group
#define NG    11             // groups (NG*GS == NKS)
#define STB   4096           // bytes of B per k-step (128n * 8u32)
#define GB    (GS * STB)     // 12288 B per group
#define MT    128

// ---------------- device scratch ----------------
__device__ float g_coord[(size_t)MAXN * K_DIM];
__device__ float g_kv[MAXN];
__device__ uint32_t g_cover[MAXN / 32];
// B image for big gemm: [4 nblk][11 grp][3 sl][128 n][8 u32]
__device__ __align__(16) uint32_t g_Vb[4 * NG * GS * 128 * 8];
// U image for rowstats: [32 ks][32 j][8 u32]
__device__ __align__(16) uint32_t g_Ub[32 * 32 * 8];
__device__ float g_xmuU[K_DIM];
__device__ float g_xcU[K_DIM];
__device__ float g_dU[K_DIM];            // xmuU - xcU
__device__ float g_change[D_DIM];

// ---------------- PTX helpers ----------------
__device__ __forceinline__ uint32_t smem_u32(const void* p) {
    uint32_t a;
    asm("{ .reg .u64 t; cvta.to.shared.u64 t, %1; cvt.u32.u64 %0, t; }" : "=r"(a) : "l"(p));
    return a;
}
#define MBAR_INIT(a, c) asm volatile("mbarrier.init.shared.b64 [%0], %1;" :: "r"(a), "r"(c) : "memory")
#define MBAR_EXPECT_TX(a, b) asm volatile("mbarrier.arrive.expect_tx.shared.b64 _, [%0], %1;" :: "r"(a), "r"(b) : "memory")
#define MBAR_WAIT(a, p) do { \
    uint32_t _m = (a), _p = (p), _d; \
    asm volatile("{ .reg .pred q; mbarrier.try_wait.parity.acquire.cta.shared::cta.b64 q, [%1], %2; selp.b32 %0,1,0,q; }" \
        : "=r"(_d) : "r"(_m), "r"(_p) : "memory"); \
    if (!_d) asm volatile("{ .reg .pred Q; WL%=: mbarrier.try_wait.parity.acquire.cta.shared::cta.b64 Q, [%0], %1, 0x989680; @Q bra.uni WD%=; bra.uni WL%=; WD%=: }" \
        :: "r"(_m), "r"(_p) : "memory"); \
} while (0)
#define FENCE_ASYNC() asm volatile("fence.proxy.async.shared::cta;" ::: "memory")

__device__ __forceinline__ void bulk_g2s(uint32_t dst, const void* src, uint32_t bytes, uint32_t mbar) {
    asm volatile("cp.async.bulk.shared::cta.global.mbarrier::complete_tx::bytes [%0], [%1], %2, [%3];"
        :: "r"(dst), "l"(src), "r"(bytes), "r"(mbar) : "memory");
}
__device__ __forceinline__ void mma16816(float* c, const uint32_t* a, const uint32_t* b) {
    asm volatile("mma.sync.aligned.m16n8k16.row.col.f32.bf16.bf16.f32 "
        "{%0,%1,%2,%3}, {%4,%5,%6,%7}, {%8,%9}, {%0,%1,%2,%3};"
        : "+f"(c[0]), "+f"(c[1]), "+f"(c[2]), "+f"(c[3])
        : "r"(a[0]), "r"(a[1]), "r"(a[2]), "r"(a[3]), "r"(b[0]), "r"(b[1]));
}
__device__ __forceinline__ uint32_t packbf(float a, float b) {
    __nv_bfloat162 r = __float22bfloat162_rn(make_float2(a, b));
    return *(uint32_t*)&r;
}

// ---------------- kernel A: small vectors + bitmap clear ----------------
__global__ void k_init(const float* __restrict__ U,
                       const float* __restrict__ zmu,
                       const float* __restrict__ xc) {
    __shared__ float s_xmuU[K_DIM], s_xcU[K_DIM];
    int t = threadIdx.x;
    for (int i = t; i < MAXN / 32; i += 512) g_cover[i] = 0u;
    if (t < 64) {
        int j = t & 31;
        bool is_mu = t < 32;
        const float* v = is_mu ? zmu : xc;
        float s = 0.f;
        for (int d = 0; d < D_DIM; ++d) s = fmaf(v[d], U[d * K_DIM + j], s);
        if (is_mu) { s_xmuU[j] = s; g_xmuU[j] = s; }
        else       { s_xcU[j]  = s; g_xcU[j]  = s; }
    }
    __syncthreads();
    if (t < 32) g_dU[t] = s_xmuU[t] - s_xcU[t];
    for (int d = t; d < D_DIM; d += blockDim.x) {
        float s = 0.f;
        #pragma unroll
        for (int j = 0; j < K_DIM; ++j)
            s = fmaf(s_xcU[j] - s_xmuU[j], U[d * K_DIM + j], s);
        g_change[d] = xc[d] - zmu[d] - s;
    }
}

// ---------------- kernel P: permuted bf16 V image ----------------
__global__ void k_prepV(const float* __restrict__ V) {
    int pos = threadIdx.x;
    if (pos >= 264) return;
    int d = blockIdx.x;
    int ks = pos >> 3, q = pos & 7;
    int k = ks * 16 + 2 * (q >> 1) + 8 * (q & 1);
    float2 v = *(const float2*)&V[(size_t)d * P_DIM + k];
    int nblk = d >> 7, n = d & 127;
    int grp = ks / GS, sl = ks % GS;
    g_Vb[((((size_t)(nblk * NG + grp) * GS + sl) * 128 + n) * 8) + q] = packbf(v.x, v.y);
}

// ---------------- kernel PU: permuted bf16 U image ----------------
__global__ void k_prepU(const float* __restrict__ U) {
    int idx = blockIdx.x * 256 + threadIdx.x;    // 0..8191
    if (idx >= 8192) return;
    int q = idx & 7, j = (idx >> 3) & 31, ks = idx >> 8;
    int d = ks * 16 + 2 * (q >> 1) + 8 * (q & 1);
    g_Ub[idx] = packbf(U[d * K_DIM + j], U[(d + 1) * K_DIM + j]);
}

// ---------------- secant ----------------
__device__ __forceinline__ float secf(float x, float egz, float zp) {
    float t = 1.f - egz * expf(-GAMMA * x);
    return t * t * x - zp;
}

// ---------------- kernel B: per-row stats via HMMA (+fused secant) ----------
#define KSTRIDE 4128          // bytes per k-step slab in A tile
#define RS_A    0             // 8 * 4128 = 33024
#define RS_U    33024         // 32768
#define RS_ZMU  65792         // 2048
#define RS_DU   67840         // 128
#define RS_ZN   67968         // 512
#define RS_CHC  68480         // 512
#define RS_SMEM 68992

__global__ __launch_bounds__(256, 3) void k_rowstats(
    const float* __restrict__ Z_all, const float* __restrict__ zmu,
    const int* __restrict__ choice, int N) {

    extern __shared__ __align__(16) char rsm[];
    int tid = threadIdx.x;
    int lane = tid & 31, w = tid >> 5;
    int gl = lane >> 2, i4 = lane & 3;
    int n0 = blockIdx.x * 128;

    float* zmuS = (float*)(rsm + RS_ZMU);
    float* dUs  = (float*)(rsm + RS_DU);
    float* s_zn = (float*)(rsm + RS_ZN);
    int*   chcS = (int*)(rsm + RS_CHC);

    for (int i = tid; i < 512; i += 256) zmuS[i] = zmu[i];
    if (tid < 32) dUs[tid] = g_dU[tid];
    for (int e = tid; e < 2048; e += 256)
        ((uint4*)(rsm + RS_U))[e] = ((const uint4*)g_Ub)[e];
    if (tid < 128) {
        int cc = choice[min(n0 + tid, N - 1)];
        chcS[tid] = cc;
        if (n0 + tid < N) atomicOr(&g_cover[cc >> 5], 1u << (cc & 31));
    }
    __syncthreads();

    float acc[4][4] = {};
    float znp[4] = {};
    int c8 = lane & 7, rq = lane >> 3;

    // conv(c): load Z chunk, subtract zmu, accumulate zn, pack bf16 A-frags
    auto conv = [&](int c) {
        #pragma unroll
        for (int p = 0; p < 4; ++p) {
            int row = p * 32 + w * 4 + rq;
            const float* zrow = Z_all + (size_t)chcS[row] * D_DIM + c * 128;
            #pragma unroll
            for (int i = 0; i < 4; ++i) {
                int col4 = c8 + 8 * i;
                float4 z = *(const float4*)&zrow[col4 * 4];
                float4 m = *(const float4*)&zmuS[c * 128 + col4 * 4];
                float z0 = z.x - m.x, z1 = z.y - m.y, z2 = z.z - m.z, z3 = z.w - m.w;
                znp[p] += z0 * z0 + z1 * z1 + z2 * z2 + z3 * z3;
                int ks = col4 >> 2, kb = (col4 & 3) * 4;
                int q0 = (kb & 6) + (kb >> 3);
                int q1 = ((kb + 2) & 6) + ((kb + 2) >> 3);
                uint32_t* A = (uint32_t*)(rsm + RS_A + ks * KSTRIDE) + row * 8;
                A[q0] = packbf(z0, z1);
                A[q1] = packbf(z2, z3);
            }
        }
    };

    #pragma unroll 1
    for (int c = 0; c < 4; ++c) {
        if (c) __syncthreads();   // A consumed by previous mma
        conv(c);
        __syncthreads();
        #pragma unroll
        for (int ks = 0; ks < 8; ++ks) {
            const char* hb = rsm + RS_A + ks * KSTRIDE + i4 * 8;
            int r = w * 16 + gl;
            uint2 u = *(const uint2*)(hb + r * 32);
            uint2 v = *(const uint2*)(hb + (r + 8) * 32);
            uint32_t a[4] = {u.x, v.x, u.y, v.y};
            const char* bb = rsm + RS_U + (c * 8 + ks) * 1024 + i4 * 8;
            #pragma unroll
            for (int nt = 0; nt < 4; ++nt) {
                uint2 b = *(const uint2*)(bb + (nt * 8 + gl) * 32);
                uint32_t br[2] = {b.x, b.y};
                mma16816(acc[nt], a, br);
            }
        }
    }

    // zn reduce over c8 group
    #pragma unroll
    for (int p = 0; p < 4; ++p) {
        float v = znp[p];
        v += __shfl_xor_sync(~0u, v, 1);
        v += __shfl_xor_sync(~0u, v, 2);
        v += __shfl_xor_sync(~0u, v, 4);
        if (c8 == 0) s_zn[p * 32 + w * 4 + rq] = v;
    }
    __syncthreads();

    // zun + coord from accumulators; acc = ZU - xmuU
    int r0 = w * 16 + gl, r1 = r0 + 8;
    float zun0 = 0.f, zun1 = 0.f;
    #pragma unroll
    for (int nt = 0; nt < 4; ++nt) {
        zun0 += acc[nt][0] * acc[nt][0] + acc[nt][1] * acc[nt][1];
        zun1 += acc[nt][2] * acc[nt][2] + acc[nt][3] * acc[nt][3];
    }
    zun0 += __shfl_xor_sync(~0u, zun0, 1); zun0 += __shfl_xor_sync(~0u, zun0, 2);
    zun1 += __shfl_xor_sync(~0u, zun1, 1); zun1 += __shfl_xor_sync(~0u, zun1, 2);
    #pragma unroll
    for (int nt = 0; nt < 4; ++nt) {
        int cc = nt * 8 + 2 * i4;
        *(float2*)&g_coord[(size_t)(n0 + r0) * K_DIM + cc] =
            make_float2(acc[nt][0] + dUs[cc], acc[nt][1] + dUs[cc + 1]);
        *(float2*)&g_coord[(size_t)(n0 + r1) * K_DIM + cc] =
            make_float2(acc[nt][2] + dUs[cc], acc[nt][3] + dUs[cc + 1]);
    }

    // fused secant: lane i4==0 solves r0, i4==1 solves r1
    if (i4 < 2) {
        int r = (i4 == 0) ? r0 : r1;
        float zun = (i4 == 0) ? zun0 : zun1;
        float zp = s_zn[r] - zun;
        float egz = expf(-GAMMA * zun);
        float x_m2 = zp * GUESS_RATIO, x_m1 = zp;
        float f_m2 = secf(x_m2, egz, zp);
        for (int it = 0; it < 100; ++it) {
            float f_m1 = secf(x_m1, egz, zp);
            float fd = f_m1 - f_m2;
            if (fabsf(fd) < TOLF) fd = (fd >= 0.f) ? TOLF : -TOLF;
            float x = x_m1 - f_m1 * (x_m1 - x_m2) / fd;
            float st = fabsf(x - x_m1);
            x_m2 = x_m1; f_m2 = f_m1; x_m1 = x;
            if (st < 3e-6f * fabsf(x) + TOLF) break;
        }
        g_kv[n0 + r] = expf(-GAMMA * (zun + x_m1));
    }
}

// ---------------- kernel F: copy uncovered rows (warp-ballot) ----------------
__global__ __launch_bounds__(256) void k_fill(const float* __restrict__ Z_all,
                                              float* __restrict__ out, int rows) {
    int wi = (blockIdx.x * 256 + threadIdx.x) >> 5;
    int lane = threadIdx.x & 31;
    int r0 = wi * 32;
    if (r0 >= rows) return;
    uint32_t need = ~g_cover[wi];
    if (r0 + 32 > rows) need &= (1u << (rows - r0)) - 1u;
    while (need) {
        int b = __ffs(need) - 1;
        need &= need - 1;
        size_t r = (size_t)(r0 + b);
        const float4* z = (const float4*)(Z_all + r * D_DIM);
        float4* o = (float4*)(out + r * D_DIM);
        #pragma unroll
        for (int i = 0; i < 4; ++i) o[lane + 32 * i] = z[lane + 32 * i];
    }
}

// ---------------- kernel C: HMMA GEMM + fused epilogue ----------------
#define OFF_B   0
#define OFF_H   49152
#define OFF_CRD 73728
#define OFF_CHG 90624
#define OFF_KV  91136
#define OFF_CHC 91648
#define OFF_IUP 92160
#define OFF_MB  93248
#define SMEM_SZ 93440

__global__ __launch_bounds__(256, 2) void k_gemm(
    const float* __restrict__ Z_all, const int* __restrict__ choice,
    float* __restrict__ out, int N) {

    extern __shared__ __align__(16) char smem[];
    uint32_t sb = smem_u32(smem);
    int tid = threadIdx.x;
    int m0 = blockIdx.x * MT;
    int d0 = blockIdx.y * 128;

    float* chgS = (float*)(smem + OFF_CHG);
    float* kvS  = (float*)(smem + OFF_KV);
    int*   chcS = (int*)(smem + OFF_CHC);
    uint16_t* iup = (uint16_t*)(smem + OFF_IUP);
    float* crdS = (float*)(smem + OFF_CRD);

    uint32_t mb[4] = {sb + OFF_MB, sb + OFF_MB + 8, sb + OFF_MB + 16, sb + OFF_MB + 24};
    const char* Vbase = (const char*)g_Vb + (size_t)blockIdx.y * NG * GB;

    if (tid == 0) {
        #pragma unroll
        for (int s = 0; s < 4; ++s) MBAR_INIT(mb[s], 1);
        FENCE_ASYNC();
        #pragma unroll
        for (int gq = 0; gq < 3; ++gq) {
            MBAR_EXPECT_TX(mb[gq], GB);
            bulk_g2s(sb + OFF_B + gq * GB, Vbase + (size_t)gq * GB, GB, mb[gq]);
        }
    }

    if (tid < K_DIM) {
        int i = tid;
        int off = i * K_DIM - (i * (i - 1)) / 2;
        for (int j = i; j < K_DIM; ++j)
            iup[off + j - i] = (uint16_t)(i | (j << 8));
    }
    if (tid < 128) {
        chgS[tid] = g_change[d0 + tid];
        int gm = m0 + tid;
        kvS[tid]  = (gm < N) ? g_kv[gm] : 0.f;
        chcS[tid] = (gm < N) ? choice[gm] : 0;
    }
    for (int e = tid; e < MT * 8; e += 256) {
        int m = e >> 3, q = e & 7;
        float4 v = ((const float4*)(g_coord + (size_t)(m0 + m) * K_DIM))[q];
        float* dst = &crdS[m * 33 + q * 4];
        dst[0] = v.x; dst[1] = v.y; dst[2] = v.z; dst[3] = v.w;
    }
    __syncthreads();

    int lane = tid & 31, wid = tid >> 5;
    int gl = lane >> 2, i4 = lane & 3;
    int warp_m0 = (wid >> 1) * 32;
    int warp_n0 = (wid & 1) * 64;

    float acc[2][8][4] = {};

    int gm_row = tid >> 1, gh = tid & 1;
    const float* cm = &crdS[gm_row * 33];

    #pragma unroll
    for (int sl = 0; sl < GS; ++sl) {
        int kbase = sl * 16;
        uint32_t w[4];
        #pragma unroll
        for (int qq = 0; qq < 4; ++qq) {
            int q = gh * 4 + qq;
            int kb = kbase + 2 * (q >> 1) + 8 * (q & 1);
            uint32_t p0 = iup[kb], p1 = iup[kb + 1];
            w[qq] = packbf(cm[p0 & 255] * cm[p0 >> 8], cm[p1 & 255] * cm[p1 >> 8]);
        }
        *(uint4*)(smem + OFF_H + sl * STB + gm_row * 32 + gh * 16) =
            make_uint4(w[0], w[1], w[2], w[3]);
    }

    #pragma unroll 1
    for (int g = 0; g < NG; ++g) {
        __syncthreads();
        if (tid == 0 && g + 3 < NG) {
            int slot = (g + 3) & 3;
            MBAR_EXPECT_TX(mb[slot], GB);
            bulk_g2s(sb + OFF_B + slot * GB, Vbase + (size_t)(g + 3) * GB, GB, mb[slot]);
        }
        MBAR_WAIT(mb[g & 3], (g >> 2) & 1);

        const char* hbuf = smem + OFF_H + (g & 1) * GB;
        const char* bbuf = smem + OFF_B + (g & 3) * GB;
        #pragma unroll
        for (int sl = 0; sl < GS; ++sl) {
            const char* hb = hbuf + sl * STB + i4 * 8;
            const char* bb = bbuf + sl * STB + i4 * 8;
            uint32_t a[2][4];
            #pragma unroll
            for (int mt = 0; mt < 2; ++mt) {
                int r = warp_m0 + mt * 16 + gl;
                uint2 u = *(const uint2*)(hb + r * 32);
                uint2 v = *(const uint2*)(hb + (r + 8) * 32);
                a[mt][0] = u.x; a[mt][1] = v.x; a[mt][2] = u.y; a[mt][3] = v.y;
            }
            #pragma unroll
            for (int nt = 0; nt < 8; ++nt) {
                int n = warp_n0 + nt * 8 + gl;
                uint2 b = *(const uint2*)(bb + n * 32);
                uint32_t br[2] = {b.x, b.y};
                mma16816(acc[0][nt], a[0], br);
                mma16816(acc[1][nt], a[1], br);
            }
        }
        if (g + 1 < NG) {
            #pragma unroll
            for (int sl = 0; sl < GS; ++sl) {
                int kbase = ((g + 1) * GS + sl) * 16;
                uint32_t w[4];
                #pragma unroll
                for (int qq = 0; qq < 4; ++qq) {
                    int q = gh * 4 + qq;
                    int kb = kbase + 2 * (q >> 1) + 8 * (q & 1);
                    uint32_t p0 = iup[kb], p1 = iup[kb + 1];
                    w[qq] = packbf(cm[p0 & 255] * cm[p0 >> 8], cm[p1 & 255] * cm[p1 >> 8]);
                }
                *(uint4*)(smem + OFF_H + ((g + 1) & 1) * GB + sl * STB + gm_row * 32 + gh * 16) =
                    make_uint4(w[0], w[1], w[2], w[3]);
            }
        }
    }

    #pragma unroll
    for (int mt = 0; mt < 2; ++mt) {
        #pragma unroll
        for (int rr = 0; rr < 2; ++rr) {
            int r = warp_m0 + mt * 16 + gl + rr * 8;
            int gm = m0 + r;
            if (gm >= N) continue;
            float kv = kvS[r];
            size_t base = (size_t)chcS[r] * D_DIM + d0 + warp_n0 + 2 * i4;
            #pragma unroll
            for (int nt = 0; nt < 8; ++nt) {
                size_t idx = base + nt * 8;
                int nl = warp_n0 + nt * 8 + 2 * i4;
                float2 z = *(const float2*)&Z_all[idx];
                float2 o;
                o.x = z.x + kv * (chgS[nl]     + acc[mt][nt][rr * 2]);
                o.y = z.y + kv * (chgS[nl + 1] + acc[mt][nt][rr * 2 + 1]);
                *(float2*)&out[idx] = o;
            }
        }
    }
}

// ---------------- launch ----------------
extern "C" void kernel_launch(void* const* d_in, const int* in_sizes, int n_in,
                              void* d_out, int out_size) {
    const float* Z_all = (const float*)d_in[0];
    const float* U     = (const float*)d_in[1];
    const float* V     = (const float*)d_in[2];
    const float* zmu   = (const float*)d_in[3];
    const float* xc    = (const float*)d_in[4];
    const int*   choice= (const int*)d_in[5];
    int N = in_sizes[5];
    float* out = (float*)d_out;
    int rows = out_size / D_DIM;

    cudaFuncSetAttribute(k_gemm, cudaFuncAttributeMaxDynamicSharedMemorySize, SMEM_SZ);
    cudaFuncSetAttribute(k_rowstats, cudaFuncAttributeMaxDynamicSharedMemorySize, RS_SMEM);

    k_init<<<1, 512>>>(U, zmu, xc);
    k_prepV<<<512, 288>>>(V);
    k_prepU<<<32, 256>>>(U);
    k_rowstats<<<(N + 127) / 128, 256, RS_SMEM>>>(Z_all, zmu, choice, N);
    k_fill<<<(rows + 255) / 256, 256>>>(Z_all, out, rows);
    dim3 grid((N + MT - 1) / MT, 4);
    k_gemm<<<grid, 256, SMEM_SZ>>>(Z_all, choice, out, N);
}

// round 16
// speedup vs baseline: 5.2086x; 1.1864x over previous
#include <cuda_runtime.h>
#include <cuda_bf16.h>
#include <cstdint>

#define D_DIM 512
#define K_DIM 32
#define P_DIM 528            // K*(K+1)/2 = 33*16
#define MAXN  100352
#define GAMMA 0.01f
#define TOLF  1e-6f
#define GUESS_RATIO (1.0f - 0.001f)

#define NKS   33             // k-steps of 16
#define GS    3              // k-steps per group
#define NG    11             // groups
#define STB   4096           // bytes per k-step tile (128 x 8 u32)
#define GB    (GS * STB)     // 12288 B per group
#define MT    128
#define NMB   784            // max m-blocks

// ---------------- device scratch ----------------
__device__ float g_coord[(size_t)MAXN * K_DIM];
__device__ float g_kv[MAXN];
__device__ uint32_t g_cover[MAXN / 32];
// B image: [4 nblk][11 grp][3 sl][128 n][8 u32]
__device__ __align__(16) uint32_t g_Vb[4 * NG * GS * 128 * 8];
// H image: [784 mblk][33 ks][128 row][8 u32]  (~106 MB)
__device__ __align__(16) uint32_t g_H[(size_t)NMB * NKS * 128 * 8];
// U image for rowstats: [32 ks][32 j][8 u32]
__device__ __align__(16) uint32_t g_Ub[32 * 32 * 8];
__device__ float g_xmuU[K_DIM];
__device__ float g_xcU[K_DIM];
__device__ float g_dU[K_DIM];
__device__ float g_change[D_DIM];

// ---------------- PTX helpers ----------------
__device__ __forceinline__ uint32_t smem_u32(const void* p) {
    uint32_t a;
    asm("{ .reg .u64 t; cvta.to.shared.u64 t, %1; cvt.u32.u64 %0, t; }" : "=r"(a) : "l"(p));
    return a;
}
#define MBAR_INIT(a, c) asm volatile("mbarrier.init.shared.b64 [%0], %1;" :: "r"(a), "r"(c) : "memory")
#define MBAR_EXPECT_TX(a, b) asm volatile("mbarrier.arrive.expect_tx.shared.b64 _, [%0], %1;" :: "r"(a), "r"(b) : "memory")
#define MBAR_WAIT(a, p) do { \
    uint32_t _m = (a), _p = (p), _d; \
    asm volatile("{ .reg .pred q; mbarrier.try_wait.parity.acquire.cta.shared::cta.b64 q, [%1], %2; selp.b32 %0,1,0,q; }" \
        : "=r"(_d) : "r"(_m), "r"(_p) : "memory"); \
    if (!_d) asm volatile("{ .reg .pred Q; WL%=: mbarrier.try_wait.parity.acquire.cta.shared::cta.b64 Q, [%0], %1, 0x989680; @Q bra.uni WD%=; bra.uni WL%=; WD%=: }" \
        :: "r"(_m), "r"(_p) : "memory"); \
} while (0)
#define FENCE_ASYNC() asm volatile("fence.proxy.async.shared::cta;" ::: "memory")

__device__ __forceinline__ void bulk_g2s(uint32_t dst, const void* src, uint32_t bytes, uint32_t mbar) {
    asm volatile("cp.async.bulk.shared::cta.global.mbarrier::complete_tx::bytes [%0], [%1], %2, [%3];"
        :: "r"(dst), "l"(src), "r"(bytes), "r"(mbar) : "memory");
}
__device__ __forceinline__ void mma16816(float* c, const uint32_t* a, const uint32_t* b) {
    asm volatile("mma.sync.aligned.m16n8k16.row.col.f32.bf16.bf16.f32 "
        "{%0,%1,%2,%3}, {%4,%5,%6,%7}, {%8,%9}, {%0,%1,%2,%3};"
        : "+f"(c[0]), "+f"(c[1]), "+f"(c[2]), "+f"(c[3])
        : "r"(a[0]), "r"(a[1]), "r"(a[2]), "r"(a[3]), "r"(b[0]), "r"(b[1]));
}
__device__ __forceinline__ uint32_t packbf(float a, float b) {
    __nv_bfloat162 r = __float22bfloat162_rn(make_float2(a, b));
    return *(uint32_t*)&r;
}

// ---------------- kernel A: small vectors + bitmap clear ----------------
__global__ void k_init(const float* __restrict__ U,
                       const float* __restrict__ zmu,
                       const float* __restrict__ xc) {
    __shared__ float s_xmuU[K_DIM], s_xcU[K_DIM];
    int t = threadIdx.x;
    for (int i = t; i < MAXN / 32; i += 512) g_cover[i] = 0u;
    if (t < 64) {
        int j = t & 31;
        bool is_mu = t < 32;
        const float* v = is_mu ? zmu : xc;
        float s = 0.f;
        for (int d = 0; d < D_DIM; ++d) s = fmaf(v[d], U[d * K_DIM + j], s);
        if (is_mu) { s_xmuU[j] = s; g_xmuU[j] = s; }
        else       { s_xcU[j]  = s; g_xcU[j]  = s; }
    }
    __syncthreads();
    if (t < 32) g_dU[t] = s_xmuU[t] - s_xcU[t];
    for (int d = t; d < D_DIM; d += blockDim.x) {
        float s = 0.f;
        #pragma unroll
        for (int j = 0; j < K_DIM; ++j)
            s = fmaf(s_xcU[j] - s_xmuU[j], U[d * K_DIM + j], s);
        g_change[d] = xc[d] - zmu[d] - s;
    }
}

// ---------------- kernel P: permuted bf16 V image ----------------
__global__ void k_prepV(const float* __restrict__ V) {
    int pos = threadIdx.x;
    if (pos >= 264) return;
    int d = blockIdx.x;
    int ks = pos >> 3, q = pos & 7;
    int k = ks * 16 + 2 * (q >> 1) + 8 * (q & 1);
    float2 v = *(const float2*)&V[(size_t)d * P_DIM + k];
    int nblk = d >> 7, n = d & 127;
    int grp = ks / GS, sl = ks % GS;
    g_Vb[((((size_t)(nblk * NG + grp) * GS + sl) * 128 + n) * 8) + q] = packbf(v.x, v.y);
}

// ---------------- kernel PU: permuted bf16 U image ----------------
__global__ void k_prepU(const float* __restrict__ U) {
    int idx = blockIdx.x * 256 + threadIdx.x;
    if (idx >= 8192) return;
    int q = idx & 7, j = (idx >> 3) & 31, ks = idx >> 8;
    int d = ks * 16 + 2 * (q >> 1) + 8 * (q & 1);
    g_Ub[idx] = packbf(U[d * K_DIM + j], U[(d + 1) * K_DIM + j]);
}

// ---------------- secant ----------------
__device__ __forceinline__ float secf(float x, float egz, float zp) {
    float t = 1.f - egz * expf(-GAMMA * x);
    return t * t * x - zp;
}

// ---------------- kernel B: per-row stats via HMMA (+fused secant) ----------
#define KSTRIDE 4128
#define RS_A    0
#define RS_U    33024
#define RS_ZMU  65792
#define RS_DU   67840
#define RS_ZN   67968
#define RS_CHC  68480
#define RS_SMEM 68992

__global__ __launch_bounds__(256, 3) void k_rowstats(
    const float* __restrict__ Z_all, const float* __restrict__ zmu,
    const int* __restrict__ choice, int N) {

    extern __shared__ __align__(16) char rsm[];
    int tid = threadIdx.x;
    int lane = tid & 31, w = tid >> 5;
    int gl = lane >> 2, i4 = lane & 3;
    int n0 = blockIdx.x * 128;

    float* zmuS = (float*)(rsm + RS_ZMU);
    float* dUs  = (float*)(rsm + RS_DU);
    float* s_zn = (float*)(rsm + RS_ZN);
    int*   chcS = (int*)(rsm + RS_CHC);

    for (int i = tid; i < 512; i += 256) zmuS[i] = zmu[i];
    if (tid < 32) dUs[tid] = g_dU[tid];
    for (int e = tid; e < 2048; e += 256)
        ((uint4*)(rsm + RS_U))[e] = ((const uint4*)g_Ub)[e];
    if (tid < 128) {
        int cc = choice[min(n0 + tid, N - 1)];
        chcS[tid] = cc;
        if (n0 + tid < N) atomicOr(&g_cover[cc >> 5], 1u << (cc & 31));
    }
    __syncthreads();

    float acc[4][4] = {};
    float znp[4] = {};
    int c8 = lane & 7, rq = lane >> 3;

    auto conv = [&](int c) {
        #pragma unroll
        for (int p = 0; p < 4; ++p) {
            int row = p * 32 + w * 4 + rq;
            const float* zrow = Z_all + (size_t)chcS[row] * D_DIM + c * 128;
            #pragma unroll
            for (int i = 0; i < 4; ++i) {
                int col4 = c8 + 8 * i;
                float4 z = *(const float4*)&zrow[col4 * 4];
                float4 m = *(const float4*)&zmuS[c * 128 + col4 * 4];
                float z0 = z.x - m.x, z1 = z.y - m.y, z2 = z.z - m.z, z3 = z.w - m.w;
                znp[p] += z0 * z0 + z1 * z1 + z2 * z2 + z3 * z3;
                int ks = col4 >> 2, kb = (col4 & 3) * 4;
                int q0 = (kb & 6) + (kb >> 3);
                int q1 = ((kb + 2) & 6) + ((kb + 2) >> 3);
                uint32_t* A = (uint32_t*)(rsm + RS_A + ks * KSTRIDE) + row * 8;
                A[q0] = packbf(z0, z1);
                A[q1] = packbf(z2, z3);
            }
        }
    };

    #pragma unroll 1
    for (int c = 0; c < 4; ++c) {
        if (c) __syncthreads();
        conv(c);
        __syncthreads();
        #pragma unroll
        for (int ks = 0; ks < 8; ++ks) {
            const char* hb = rsm + RS_A + ks * KSTRIDE + i4 * 8;
            int r = w * 16 + gl;
            uint2 u = *(const uint2*)(hb + r * 32);
            uint2 v = *(const uint2*)(hb + (r + 8) * 32);
            uint32_t a[4] = {u.x, v.x, u.y, v.y};
            const char* bb = rsm + RS_U + (c * 8 + ks) * 1024 + i4 * 8;
            #pragma unroll
            for (int nt = 0; nt < 4; ++nt) {
                uint2 b = *(const uint2*)(bb + (nt * 8 + gl) * 32);
                uint32_t br[2] = {b.x, b.y};
                mma16816(acc[nt], a, br);
            }
        }
    }

    #pragma unroll
    for (int p = 0; p < 4; ++p) {
        float v = znp[p];
        v += __shfl_xor_sync(~0u, v, 1);
        v += __shfl_xor_sync(~0u, v, 2);
        v += __shfl_xor_sync(~0u, v, 4);
        if (c8 == 0) s_zn[p * 32 + w * 4 + rq] = v;
    }
    __syncthreads();

    int r0 = w * 16 + gl, r1 = r0 + 8;
    float zun0 = 0.f, zun1 = 0.f;
    #pragma unroll
    for (int nt = 0; nt < 4; ++nt) {
        zun0 += acc[nt][0] * acc[nt][0] + acc[nt][1] * acc[nt][1];
        zun1 += acc[nt][2] * acc[nt][2] + acc[nt][3] * acc[nt][3];
    }
    zun0 += __shfl_xor_sync(~0u, zun0, 1); zun0 += __shfl_xor_sync(~0u, zun0, 2);
    zun1 += __shfl_xor_sync(~0u, zun1, 1); zun1 += __shfl_xor_sync(~0u, zun1, 2);
    #pragma unroll
    for (int nt = 0; nt < 4; ++nt) {
        int cc = nt * 8 + 2 * i4;
        *(float2*)&g_coord[(size_t)(n0 + r0) * K_DIM + cc] =
            make_float2(acc[nt][0] + dUs[cc], acc[nt][1] + dUs[cc + 1]);
        *(float2*)&g_coord[(size_t)(n0 + r1) * K_DIM + cc] =
            make_float2(acc[nt][2] + dUs[cc], acc[nt][3] + dUs[cc + 1]);
    }

    if (i4 < 2) {
        int r = (i4 == 0) ? r0 : r1;
        float zun = (i4 == 0) ? zun0 : zun1;
        float zp = s_zn[r] - zun;
        float egz = expf(-GAMMA * zun);
        float x_m2 = zp * GUESS_RATIO, x_m1 = zp;
        float f_m2 = secf(x_m2, egz, zp);
        for (int it = 0; it < 100; ++it) {
            float f_m1 = secf(x_m1, egz, zp);
            float fd = f_m1 - f_m2;
            if (fabsf(fd) < TOLF) fd = (fd >= 0.f) ? TOLF : -TOLF;
            float x = x_m1 - f_m1 * (x_m1 - x_m2) / fd;
            float st = fabsf(x - x_m1);
            x_m2 = x_m1; f_m2 = f_m1; x_m1 = x;
            if (st < 3e-6f * fabsf(x) + TOLF) break;
        }
        g_kv[n0 + r] = expf(-GAMMA * (zun + x_m1));
    }
}

// ---------------- kernel H: generate permuted bf16 H image ----------------
__global__ __launch_bounds__(256) void k_hgen(int N) {
    __shared__ float crdS[128 * 33];
    __shared__ uint16_t iup[P_DIM];
    int tid = threadIdx.x;
    int m0 = blockIdx.x * 128;

    if (tid < K_DIM) {
        int i = tid;
        int off = i * K_DIM - (i * (i - 1)) / 2;
        for (int j = i; j < K_DIM; ++j)
            iup[off + j - i] = (uint16_t)(i | (j << 8));
    }
    for (int e = tid; e < MT * 8; e += 256) {
        int m = e >> 3, q = e & 7;
        float4 v = (m0 + m < N) ? ((const float4*)(g_coord + (size_t)(m0 + m) * K_DIM))[q]
                                : make_float4(0.f, 0.f, 0.f, 0.f);
        float* dst = &crdS[m * 33 + q * 4];
        dst[0] = v.x; dst[1] = v.y; dst[2] = v.z; dst[3] = v.w;
    }
    __syncthreads();

    int row = tid >> 1, gh = tid & 1;
    const float* cm = &crdS[row * 33];
    uint32_t* Hb = g_H + ((size_t)blockIdx.x * NKS) * 128 * 8;

    #pragma unroll 1
    for (int ks = 0; ks < NKS; ++ks) {
        int kbase = ks * 16;
        uint32_t w[4];
        #pragma unroll
        for (int qq = 0; qq < 4; ++qq) {
            int q = gh * 4 + qq;
            int kb = kbase + 2 * (q >> 1) + 8 * (q & 1);
            uint32_t p0 = iup[kb], p1 = iup[kb + 1];
            w[qq] = packbf(cm[p0 & 255] * cm[p0 >> 8], cm[p1 & 255] * cm[p1 >> 8]);
        }
        *(uint4*)(Hb + ((size_t)ks * 128 + row) * 8 + gh * 4) =
            make_uint4(w[0], w[1], w[2], w[3]);
    }
}

// ---------------- kernel F: copy uncovered rows ----------------
__global__ __launch_bounds__(256) void k_fill(const float* __restrict__ Z_all,
                                              float* __restrict__ out, int rows) {
    int wi = (blockIdx.x * 256 + threadIdx.x) >> 5;
    int lane = threadIdx.x & 31;
    int r0 = wi * 32;
    if (r0 >= rows) return;
    uint32_t need = ~g_cover[wi];
    if (r0 + 32 > rows) need &= (1u << (rows - r0)) - 1u;
    while (need) {
        int b = __ffs(need) - 1;
        need &= need - 1;
        size_t r = (size_t)(r0 + b);
        const float4* z = (const float4*)(Z_all + r * D_DIM);
        float4* o = (float4*)(out + r * D_DIM);
        #pragma unroll
        for (int i = 0; i < 4; ++i) o[lane + 32 * i] = z[lane + 32 * i];
    }
}

// ---------------- kernel C: pure HMMA GEMM + fused epilogue ----------------
#define OFF_B   0               // 4 * 12288
#define OFF_HR  49152           // 4 * 12288
#define OFF_CHG 98304
#define OFF_KV  98816
#define OFF_CHC 99328
#define OFF_MB  99840
#define SMEM_SZ 99968

__global__ __launch_bounds__(256, 2) void k_gemm(
    const float* __restrict__ Z_all, const int* __restrict__ choice,
    float* __restrict__ out, int N) {

    extern __shared__ __align__(16) char smem[];
    uint32_t sb = smem_u32(smem);
    int tid = threadIdx.x;
    int d0 = blockIdx.x * 128;      // nblk fastest -> H shared via L2
    int m0 = blockIdx.y * MT;

    float* chgS = (float*)(smem + OFF_CHG);
    float* kvS  = (float*)(smem + OFF_KV);
    int*   chcS = (int*)(smem + OFF_CHC);

    uint32_t mb[4] = {sb + OFF_MB, sb + OFF_MB + 8, sb + OFF_MB + 16, sb + OFF_MB + 24};
    const char* Vbase = (const char*)g_Vb + (size_t)blockIdx.x * NG * GB;
    const char* Hbase = (const char*)g_H + (size_t)blockIdx.y * NKS * STB;

    if (tid == 0) {
        #pragma unroll
        for (int s = 0; s < 4; ++s) MBAR_INIT(mb[s], 1);
        FENCE_ASYNC();
        #pragma unroll
        for (int gq = 0; gq < 3; ++gq) {
            MBAR_EXPECT_TX(mb[gq], 2 * GB);
            bulk_g2s(sb + OFF_B  + gq * GB, Vbase + (size_t)gq * GB, GB, mb[gq]);
            bulk_g2s(sb + OFF_HR + gq * GB, Hbase + (size_t)gq * GB, GB, mb[gq]);
        }
    }

    if (tid < 128) {
        chgS[tid] = g_change[d0 + tid];
        int gm = m0 + tid;
        kvS[tid]  = (gm < N) ? g_kv[gm] : 0.f;
        chcS[tid] = (gm < N) ? choice[gm] : 0;
    }
    __syncthreads();

    int lane = tid & 31, wid = tid >> 5;
    int gl = lane >> 2, i4 = lane & 3;
    int warp_m0 = (wid >> 1) * 32;
    int warp_n0 = (wid & 1) * 64;

    float acc[2][8][4] = {};

    #pragma unroll 1
    for (int g = 0; g < NG; ++g) {
        __syncthreads();
        if (tid == 0 && g + 3 < NG) {
            int slot = (g + 3) & 3;
            MBAR_EXPECT_TX(mb[slot], 2 * GB);
            bulk_g2s(sb + OFF_B  + slot * GB, Vbase + (size_t)(g + 3) * GB, GB, mb[slot]);
            bulk_g2s(sb + OFF_HR + slot * GB, Hbase + (size_t)(g + 3) * GB, GB, mb[slot]);
        }
        MBAR_WAIT(mb[g & 3], (g >> 2) & 1);

        const char* hbuf = smem + OFF_HR + (g & 3) * GB;
        const char* bbuf = smem + OFF_B  + (g & 3) * GB;
        #pragma unroll
        for (int sl = 0; sl < GS; ++sl) {
            const char* hb = hbuf + sl * STB + i4 * 8;
            const char* bb = bbuf + sl * STB + i4 * 8;
            uint32_t a[2][4];
            #pragma unroll
            for (int mt = 0; mt < 2; ++mt) {
                int r = warp_m0 + mt * 16 + gl;
                uint2 u = *(const uint2*)(hb + r * 32);
                uint2 v = *(const uint2*)(hb + (r + 8) * 32);
                a[mt][0] = u.x; a[mt][1] = v.x; a[mt][2] = u.y; a[mt][3] = v.y;
            }
            #pragma unroll
            for (int nt = 0; nt < 8; ++nt) {
                int n = warp_n0 + nt * 8 + gl;
                uint2 b = *(const uint2*)(bb + n * 32);
                uint32_t br[2] = {b.x, b.y};
                mma16816(acc[0][nt], a[0], br);
                mma16816(acc[1][nt], a[1], br);
            }
        }
    }

    #pragma unroll
    for (int mt = 0; mt < 2; ++mt) {
        #pragma unroll
        for (int rr = 0; rr < 2; ++rr) {
            int r = warp_m0 + mt * 16 + gl + rr * 8;
            int gm = m0 + r;
            if (gm >= N) continue;
            float kv = kvS[r];
            size_t base = (size_t)chcS[r] * D_DIM + d0 + warp_n0 + 2 * i4;
            #pragma unroll
            for (int nt = 0; nt < 8; ++nt) {
                size_t idx = base + nt * 8;
                int nl = warp_n0 + nt * 8 + 2 * i4;
                float2 z = *(const float2*)&Z_all[idx];
                float2 o;
                o.x = z.x + kv * (chgS[nl]     + acc[mt][nt][rr * 2]);
                o.y = z.y + kv * (chgS[nl + 1] + acc[mt][nt][rr * 2 + 1]);
                *(float2*)&out[idx] = o;
            }
        }
    }
}

// ---------------- launch ----------------
extern "C" void kernel_launch(void* const* d_in, const int* in_sizes, int n_in,
                              void* d_out, int out_size) {
    const float* Z_all = (const float*)d_in[0];
    const float* U     = (const float*)d_in[1];
    const float* V     = (const float*)d_in[2];
    const float* zmu   = (const float*)d_in[3];
    const float* xc    = (const float*)d_in[4];
    const int*   choice= (const int*)d_in[5];
    int N = in_sizes[5];
    float* out = (float*)d_out;
    int rows = out_size / D_DIM;
    int mblks = (N + MT - 1) / MT;

    cudaFuncSetAttribute(k_gemm, cudaFuncAttributeMaxDynamicSharedMemorySize, SMEM_SZ);
    cudaFuncSetAttribute(k_rowstats, cudaFuncAttributeMaxDynamicSharedMemorySize, RS_SMEM);

    k_init<<<1, 512>>>(U, zmu, xc);
    k_prepV<<<512, 288>>>(V);
    k_prepU<<<32, 256>>>(U);
    k_rowstats<<<mblks, 256, RS_SMEM>>>(Z_all, zmu, choice, N);
    k_hgen<<<mblks, 256>>>(N);
    k_fill<<<(rows + 255) / 256, 256>>>(Z_all, out, rows);
    dim3 grid(4, mblks);
    k_gemm<<<grid, 256, SMEM_SZ>>>(Z_all, choice, out, N);
}